// round 1
// baseline (speedup 1.0000x reference)
#include <cuda_runtime.h>

// Problem constants
#define BATCH 8
#define C 256
#define HW 4096
#define JT 64     // j-tile per CTA (main)
#define IT 64     // i-tile (main)
#define PT 64     // pixel tile (prep)

// Scratch: normalized x and transformed t, both (B, C, HW) fp32
__device__ float g_xn[(size_t)BATCH * C * HW];
__device__ float g_t [(size_t)BATCH * C * HW];

// ---------------------------------------------------------------------------
// Prep: per (batch, 64-pixel tile): channel L2-normalize x -> g_xn,
//       and t = W @ x + bias -> g_t
// smem: xs[C][68], Wsm[32][261], invn[64]
// ---------------------------------------------------------------------------
__global__ void __launch_bounds__(256, 1)
prep_kernel(const float* __restrict__ x, const float* __restrict__ W,
            const float* __restrict__ bias)
{
    extern __shared__ float sm[];
    float* xs   = sm;                  // C * 68
    float* Wsm  = xs + C * 68;         // 32 * 261
    float* invn = Wsm + 32 * 261;      // 64

    const int p0  = blockIdx.x * PT;
    const int b   = blockIdx.y;
    const int tid = threadIdx.x;
    const float* xb = x + (size_t)b * C * HW;

    // Load x tile (C x 64) into smem, padded stride 68
    #pragma unroll
    for (int r = 0; r < 16; ++r) {
        int f4 = r * 256 + tid;
        int c  = f4 >> 4;        // 16 float4 per row
        int kq = f4 & 15;
        float4 v = *reinterpret_cast<const float4*>(xb + (size_t)c * HW + p0 + kq * 4);
        *reinterpret_cast<float4*>(xs + c * 68 + kq * 4) = v;
    }
    __syncthreads();

    // Per-pixel channel norms
    if (tid < 64) {
        float s = 0.f;
        #pragma unroll 8
        for (int c = 0; c < C; ++c) { float v = xs[c * 68 + tid]; s += v * v; }
        invn[tid] = 1.0f / fmaxf(sqrtf(s), 1e-12f);
    }
    __syncthreads();

    // Write xn = x * invn
    float* xnb = g_xn + (size_t)b * C * HW;
    #pragma unroll
    for (int r = 0; r < 16; ++r) {
        int f4 = r * 256 + tid;
        int c  = f4 >> 4;
        int kq = f4 & 15;
        const float* src = xs + c * 68 + kq * 4;
        float4 v;
        v.x = src[0] * invn[kq * 4 + 0];
        v.y = src[1] * invn[kq * 4 + 1];
        v.z = src[2] * invn[kq * 4 + 2];
        v.w = src[3] * invn[kq * 4 + 3];
        *reinterpret_cast<float4*>(xnb + (size_t)c * HW + p0 + kq * 4) = v;
    }

    // t[o][p] = sum_k W[o][k] * x[k][p] + bias[o]
    const int tx = tid & 31;   // o-direction (o = tx + 32*i)
    const int ty = tid >> 5;   // p-direction (p = ty*8 + j)
    float acc[8][8];
    #pragma unroll
    for (int i = 0; i < 8; ++i)
        #pragma unroll
        for (int j = 0; j < 8; ++j) acc[i][j] = 0.f;

    for (int k0 = 0; k0 < C; k0 += 32) {
        __syncthreads();
        // Stage W chunk transposed: Wsm[kk][o], stride 261 (conflict-free-ish)
        #pragma unroll
        for (int r = 0; r < 8; ++r) {
            int f4 = r * 256 + tid;
            int o  = f4 >> 3;   // 8 float4 per o-row of 32 k
            int kq = f4 & 7;
            float4 v = *reinterpret_cast<const float4*>(W + (size_t)o * C + k0 + kq * 4);
            Wsm[(kq * 4 + 0) * 261 + o] = v.x;
            Wsm[(kq * 4 + 1) * 261 + o] = v.y;
            Wsm[(kq * 4 + 2) * 261 + o] = v.z;
            Wsm[(kq * 4 + 3) * 261 + o] = v.w;
        }
        __syncthreads();
        #pragma unroll 4
        for (int kk = 0; kk < 32; ++kk) {
            float wv[8], xv[8];
            #pragma unroll
            for (int i = 0; i < 8; ++i) wv[i] = Wsm[kk * 261 + tx + 32 * i];
            #pragma unroll
            for (int j = 0; j < 8; ++j) xv[j] = xs[(k0 + kk) * 68 + ty * 8 + j];
            #pragma unroll
            for (int i = 0; i < 8; ++i)
                #pragma unroll
                for (int j = 0; j < 8; ++j)
                    acc[i][j] = fmaf(wv[i], xv[j], acc[i][j]);
        }
    }

    float* tb = g_t + (size_t)b * C * HW;
    #pragma unroll
    for (int i = 0; i < 8; ++i) {
        int o = tx + 32 * i;
        float bo = __ldg(bias + o);
        #pragma unroll
        for (int j = 0; j < 8; j += 4) {
            float4 v;
            v.x = acc[i][j + 0] + bo;
            v.y = acc[i][j + 1] + bo;
            v.z = acc[i][j + 2] + bo;
            v.w = acc[i][j + 3] + bo;
            *reinterpret_cast<float4*>(tb + (size_t)o * HW + p0 + ty * 8 + j) = v;
        }
    }
}

// ---------------------------------------------------------------------------
// Main: per (batch, 64-col j-tile):
//   out[:, jT] = sum over i-tiles of  T_i (256 x 64)  @  (Xn_i^T Xn_j)^2 (64 x 64)
// smem: xnj[C][68], xni[C][68], ti[C][65], q[64][68]
// ---------------------------------------------------------------------------
__global__ void __launch_bounds__(256, 1)
ppm_main(float* __restrict__ out)
{
    extern __shared__ float sm[];
    float* xnj = sm;                  // C*68  = 17408
    float* xni = xnj + C * 68;        // C*68  = 17408
    float* ti  = xni + C * 68;        // C*65  = 16640
    float* q   = ti  + C * 65;        // 64*68 =  4352

    const int j0  = blockIdx.x * JT;
    const int b   = blockIdx.y;
    const int tid = threadIdx.x;

    const float* xnb = g_xn + (size_t)b * C * HW;
    const float* tb  = g_t  + (size_t)b * C * HW;

    // Load xnj (persistent)
    #pragma unroll
    for (int r = 0; r < 16; ++r) {
        int f4 = r * 256 + tid;
        int c  = f4 >> 4;
        int kq = f4 & 15;
        float4 v = *reinterpret_cast<const float4*>(xnb + (size_t)c * HW + j0 + kq * 4);
        *reinterpret_cast<float4*>(xnj + c * 68 + kq * 4) = v;
    }

    // Phase A thread map: ig = i-group (4 rows), jg = j-group (4 cols)
    const int ig = tid & 15;
    const int jg = tid >> 4;
    // Phase B thread map: cg (c = cg + 32u), jg2 (j = jg2*8 + v)
    const int cg  = tid & 31;
    const int jg2 = tid >> 5;

    float acc[8][8];
    #pragma unroll
    for (int u = 0; u < 8; ++u)
        #pragma unroll
        for (int v = 0; v < 8; ++v) acc[u][v] = 0.f;

    for (int i0 = 0; i0 < HW; i0 += IT) {
        __syncthreads();   // protect smem from previous iteration's readers

        // Load xni (float4) and ti (scalars into stride-65) for this i-tile
        #pragma unroll
        for (int r = 0; r < 16; ++r) {
            int f4 = r * 256 + tid;
            int c  = f4 >> 4;
            int kq = f4 & 15;
            float4 v = *reinterpret_cast<const float4*>(xnb + (size_t)c * HW + i0 + kq * 4);
            *reinterpret_cast<float4*>(xni + c * 68 + kq * 4) = v;
            float4 w = *reinterpret_cast<const float4*>(tb + (size_t)c * HW + i0 + kq * 4);
            float* d = ti + c * 65 + kq * 4;
            d[0] = w.x; d[1] = w.y; d[2] = w.z; d[3] = w.w;
        }
        __syncthreads();

        // Phase A: S-tile (64x64) = Xni^T Xnj over 256 channels; q = S*S
        {
            float s[4][4];
            #pragma unroll
            for (int a = 0; a < 4; ++a)
                #pragma unroll
                for (int e = 0; e < 4; ++e) s[a][e] = 0.f;
            #pragma unroll 4
            for (int c = 0; c < C; ++c) {
                float4 xi = *reinterpret_cast<const float4*>(xni + c * 68 + ig * 4);
                float4 xj = *reinterpret_cast<const float4*>(xnj + c * 68 + jg * 4);
                float xia[4] = {xi.x, xi.y, xi.z, xi.w};
                float xja[4] = {xj.x, xj.y, xj.z, xj.w};
                #pragma unroll
                for (int a = 0; a < 4; ++a)
                    #pragma unroll
                    for (int e = 0; e < 4; ++e)
                        s[a][e] = fmaf(xia[a], xja[e], s[a][e]);
            }
            #pragma unroll
            for (int a = 0; a < 4; ++a) {
                float4 v;
                v.x = s[a][0] * s[a][0];
                v.y = s[a][1] * s[a][1];
                v.z = s[a][2] * s[a][2];
                v.w = s[a][3] * s[a][3];
                *reinterpret_cast<float4*>(q + (ig * 4 + a) * 68 + jg * 4) = v;
            }
        }
        __syncthreads();

        // Phase B: acc[c][j] += ti[c][k] * q[k][j] over k in i-tile
        #pragma unroll 2
        for (int k = 0; k < IT; ++k) {
            float tv[8];
            #pragma unroll
            for (int u = 0; u < 8; ++u)
                tv[u] = ti[(cg + 32 * u) * 65 + k];   // conflict-free: bank = cg+k
            float4 q0 = *reinterpret_cast<const float4*>(q + k * 68 + jg2 * 8);
            float4 q1 = *reinterpret_cast<const float4*>(q + k * 68 + jg2 * 8 + 4);
            float qv[8] = {q0.x, q0.y, q0.z, q0.w, q1.x, q1.y, q1.z, q1.w};
            #pragma unroll
            for (int u = 0; u < 8; ++u)
                #pragma unroll
                for (int v = 0; v < 8; ++v)
                    acc[u][v] = fmaf(tv[u], qv[v], acc[u][v]);
        }
    }

    // Write out[b][c][j]
    float* ob = out + (size_t)b * C * HW;
    #pragma unroll
    for (int u = 0; u < 8; ++u) {
        int c = cg + 32 * u;
        #pragma unroll
        for (int v = 0; v < 8; v += 4) {
            float4 w;
            w.x = acc[u][v + 0];
            w.y = acc[u][v + 1];
            w.z = acc[u][v + 2];
            w.w = acc[u][v + 3];
            *reinterpret_cast<float4*>(ob + (size_t)c * HW + j0 + jg2 * 8 + v) = w;
        }
    }
}

// ---------------------------------------------------------------------------
extern "C" void kernel_launch(void* const* d_in, const int* in_sizes, int n_in,
                              void* d_out, int out_size)
{
    const float* x    = (const float*)d_in[0];
    const float* W    = (const float*)d_in[1];
    const float* bias = (const float*)d_in[2];
    float* out        = (float*)d_out;

    const int PREP_SMEM = (C * 68 + 32 * 261 + 64) * 4;                  // ~103 KB
    const int MAIN_SMEM = (C * 68 + C * 68 + C * 65 + IT * 68) * 4;      // ~218 KB

    cudaFuncSetAttribute(prep_kernel, cudaFuncAttributeMaxDynamicSharedMemorySize, PREP_SMEM);
    cudaFuncSetAttribute(ppm_main,    cudaFuncAttributeMaxDynamicSharedMemorySize, MAIN_SMEM);

    dim3 g1(HW / PT, BATCH);
    prep_kernel<<<g1, 256, PREP_SMEM>>>(x, W, bias);

    dim3 g2(HW / JT, BATCH);
    ppm_main<<<g2, 256, MAIN_SMEM>>>(out);
}

// round 3
// speedup vs baseline: 3.0994x; 3.0994x over previous
#include <cuda_runtime.h>

#define BATCH 8
#define C 256
#define HW 4096
#define JT 64     // j-tile per CTA
#define ITile 64  // i-tile
#define PT 64     // prep pixel tile

// Scratch: xnT pixel-major (B, HW, C) and t c-major (B, C, HW); tf32-rounded fp32
__device__ float g_xnT[(size_t)BATCH * HW * C];
__device__ float g_t  [(size_t)BATCH * C * HW];

__device__ __forceinline__ float tf32r(float x) {
    unsigned b;
    asm("cvt.rna.tf32.f32 %0, %1;" : "=r"(b) : "f"(x));
    return __uint_as_float(b);
}

// m16n8k8 tf32 mma, fp32 accumulate (standard PTX, works on non-'a' sm_103 target)
__device__ __forceinline__ void mma_tf32(float d[4], float a0, float a1, float a2, float a3,
                                         float b0, float b1) {
    asm volatile(
        "mma.sync.aligned.m16n8k8.row.col.f32.tf32.tf32.f32 "
        "{%0,%1,%2,%3}, {%4,%5,%6,%7}, {%8,%9}, {%0,%1,%2,%3};"
        : "+f"(d[0]), "+f"(d[1]), "+f"(d[2]), "+f"(d[3])
        : "r"(__float_as_uint(a0)), "r"(__float_as_uint(a1)),
          "r"(__float_as_uint(a2)), "r"(__float_as_uint(a3)),
          "r"(__float_as_uint(b0)), "r"(__float_as_uint(b1)));
}

// ---------------------------------------------------------------------------
// Prep: normalize -> g_xnT (pixel-major, tf32), t = W@x + bias -> g_t (tf32)
// ---------------------------------------------------------------------------
__global__ void __launch_bounds__(256, 1)
prep_kernel(const float* __restrict__ x, const float* __restrict__ W,
            const float* __restrict__ bias)
{
    extern __shared__ float sm[];
    float* xs   = sm;                  // C * 68
    float* Wsm  = xs + C * 68;         // 32 * 261
    float* invn = Wsm + 32 * 261;      // 64

    const int p0  = blockIdx.x * PT;
    const int b   = blockIdx.y;
    const int tid = threadIdx.x;
    const float* xb = x + (size_t)b * C * HW;

    #pragma unroll
    for (int r = 0; r < 16; ++r) {
        int f4 = r * 256 + tid;
        int c  = f4 >> 4;
        int kq = f4 & 15;
        float4 v = *reinterpret_cast<const float4*>(xb + (size_t)c * HW + p0 + kq * 4);
        *reinterpret_cast<float4*>(xs + c * 68 + kq * 4) = v;
    }
    __syncthreads();

    if (tid < 64) {
        float s = 0.f;
        #pragma unroll 8
        for (int c = 0; c < C; ++c) { float v = xs[c * 68 + tid]; s += v * v; }
        invn[tid] = 1.0f / fmaxf(sqrtf(s), 1e-12f);
    }
    __syncthreads();

    // xnT[p][c] = x[c][p] * invn[p], tf32-rounded, pixel-major
    {
        int p   = tid & 63;
        int grp = tid >> 6;
        float inv = invn[p];
        float* dst = g_xnT + ((size_t)b * HW + p0 + p) * C;
        #pragma unroll
        for (int cc = 0; cc < 16; ++cc) {
            int c = grp * 64 + cc * 4;
            float4 v;
            v.x = tf32r(xs[(c + 0) * 68 + p] * inv);
            v.y = tf32r(xs[(c + 1) * 68 + p] * inv);
            v.z = tf32r(xs[(c + 2) * 68 + p] * inv);
            v.w = tf32r(xs[(c + 3) * 68 + p] * inv);
            *reinterpret_cast<float4*>(dst + c) = v;
        }
    }

    // t = W @ x + bias (SIMT GEMM), tf32-rounded
    const int tx = tid & 31;
    const int ty = tid >> 5;
    float acc[8][8];
    #pragma unroll
    for (int i = 0; i < 8; ++i)
        #pragma unroll
        for (int j = 0; j < 8; ++j) acc[i][j] = 0.f;

    for (int k0 = 0; k0 < C; k0 += 32) {
        __syncthreads();
        #pragma unroll
        for (int r = 0; r < 8; ++r) {
            int f4 = r * 256 + tid;
            int o  = f4 >> 3;
            int kq = f4 & 7;
            float4 v = *reinterpret_cast<const float4*>(W + (size_t)o * C + k0 + kq * 4);
            Wsm[(kq * 4 + 0) * 261 + o] = v.x;
            Wsm[(kq * 4 + 1) * 261 + o] = v.y;
            Wsm[(kq * 4 + 2) * 261 + o] = v.z;
            Wsm[(kq * 4 + 3) * 261 + o] = v.w;
        }
        __syncthreads();
        #pragma unroll 4
        for (int kk = 0; kk < 32; ++kk) {
            float wv[8], xv[8];
            #pragma unroll
            for (int i = 0; i < 8; ++i) wv[i] = Wsm[kk * 261 + tx + 32 * i];
            #pragma unroll
            for (int j = 0; j < 8; ++j) xv[j] = xs[(k0 + kk) * 68 + ty * 8 + j];
            #pragma unroll
            for (int i = 0; i < 8; ++i)
                #pragma unroll
                for (int j = 0; j < 8; ++j)
                    acc[i][j] = fmaf(wv[i], xv[j], acc[i][j]);
        }
    }

    float* tb = g_t + (size_t)b * C * HW;
    #pragma unroll
    for (int i = 0; i < 8; ++i) {
        int o = tx + 32 * i;
        float bo = __ldg(bias + o);
        #pragma unroll
        for (int j = 0; j < 8; j += 4) {
            float4 v;
            v.x = tf32r(acc[i][j + 0] + bo);
            v.y = tf32r(acc[i][j + 1] + bo);
            v.z = tf32r(acc[i][j + 2] + bo);
            v.w = tf32r(acc[i][j + 3] + bo);
            *reinterpret_cast<float4*>(tb + (size_t)o * HW + p0 + ty * 8 + j) = v;
        }
    }
}

// ---------------------------------------------------------------------------
// Main: per (batch, 64-j tile), mma.sync tf32 for both GEMMs.
// SMEM: xnj[64][260], xni[64][260], ts[256][68], qs[64][72]  (221,184 B)
// ---------------------------------------------------------------------------
__global__ void __launch_bounds__(256, 1)
ppm_main(float* __restrict__ out)
{
    extern __shared__ float sm[];
    float* xnj = sm;                   // 64 * 260
    float* xni = xnj + 64 * 260;       // 64 * 260
    float* ts  = xni + 64 * 260;       // 256 * 68
    float* qs  = ts  + 256 * 68;       // 64 * 72

    const int j0  = blockIdx.x * JT;
    const int b   = blockIdx.y;
    const int tid = threadIdx.x;
    const int wid  = tid >> 5;
    const int lane = tid & 31;
    const int grp  = lane >> 2;   // 0..7
    const int qd   = lane & 3;    // 0..3

    // GEMM1 warp map: 4 (M=i) x 2 (N=j)
    const int wm = wid & 3;
    const int wn = wid >> 2;
    // GEMM2 warp map: warp owns c rows [wid*32, wid*32+32)
    const int c_base = wid * 32;

    // Load persistent xnj (64 pixels x 256 c)
    {
        const float4* gj = reinterpret_cast<const float4*>(g_xnT + ((size_t)b * HW + j0) * C);
        #pragma unroll
        for (int r = 0; r < 16; ++r) {
            int f4 = r * 256 + tid;
            int row = f4 >> 6, col = f4 & 63;
            *reinterpret_cast<float4*>(xnj + row * 260 + col * 4) = gj[row * 64 + col];
        }
    }

    // Persistent GEMM2 accumulators: 2 m16-strips x 8 n-tiles x 4 regs
    float acc[2][8][4];
    #pragma unroll
    for (int s = 0; s < 2; ++s)
        #pragma unroll
        for (int t = 0; t < 8; ++t)
            #pragma unroll
            for (int r = 0; r < 4; ++r) acc[s][t][r] = 0.f;

    for (int it = 0; it < HW / ITile; ++it) {
        const int i0 = it * ITile;
        __syncthreads();   // previous iteration done reading xni/ts/qs

        // Load xni (64 x 256) and ts (256 x 64)
        {
            const float4* gi = reinterpret_cast<const float4*>(g_xnT + ((size_t)b * HW + i0) * C);
            #pragma unroll
            for (int r = 0; r < 16; ++r) {
                int f4 = r * 256 + tid;
                int row = f4 >> 6, col = f4 & 63;
                *reinterpret_cast<float4*>(xni + row * 260 + col * 4) = gi[row * 64 + col];
            }
            const float* gt = g_t + (size_t)b * C * HW + i0;
            #pragma unroll
            for (int r = 0; r < 16; ++r) {
                int f4 = r * 256 + tid;
                int row = f4 >> 4, col = f4 & 15;
                *reinterpret_cast<float4*>(ts + row * 68 + col * 4) =
                    *reinterpret_cast<const float4*>(gt + (size_t)row * HW + col * 4);
            }
        }
        __syncthreads();

        // --- GEMM1: S[i][j] = Xn_i . Xn_j^T  (M=64, N=64, K=256) ---
        float d[4][4];
        #pragma unroll
        for (int t = 0; t < 4; ++t)
            #pragma unroll
            for (int r = 0; r < 4; ++r) d[t][r] = 0.f;

        const float* arow0 = xni + (wm * 16 + grp) * 260;
        const float* arow1 = arow0 + 8 * 260;
        #pragma unroll 8
        for (int kk = 0; kk < 32; ++kk) {
            const int k0 = kk * 8;
            float a0 = arow0[k0 + qd];
            float a1 = arow1[k0 + qd];
            float a2 = arow0[k0 + qd + 4];
            float a3 = arow1[k0 + qd + 4];
            #pragma unroll
            for (int t = 0; t < 4; ++t) {
                const float* bp = xnj + (wn * 32 + t * 8 + grp) * 260 + k0 + qd;
                mma_tf32(d[t], a0, a1, a2, a3, bp[0], bp[4]);
            }
        }

        // Square, tf32-round, store to qs[k=i][n=j] stride 72
        {
            const int r0 = wm * 16 + grp;
            #pragma unroll
            for (int t = 0; t < 4; ++t) {
                const int nb = wn * 32 + t * 8 + qd * 2;
                qs[r0 * 72 + nb + 0]       = tf32r(d[t][0] * d[t][0]);
                qs[r0 * 72 + nb + 1]       = tf32r(d[t][1] * d[t][1]);
                qs[(r0 + 8) * 72 + nb + 0] = tf32r(d[t][2] * d[t][2]);
                qs[(r0 + 8) * 72 + nb + 1] = tf32r(d[t][3] * d[t][3]);
            }
        }
        __syncthreads();

        // --- GEMM2: out[c][j] += t[c][i] * q[i][j]  (M=256, N=64, K=64) ---
        #pragma unroll
        for (int kk = 0; kk < 8; ++kk) {
            const int k0 = kk * 8;
            float bf0[8], bf1[8];
            #pragma unroll
            for (int t = 0; t < 8; ++t) {
                const float* bp = qs + (k0 + qd) * 72 + t * 8 + grp;
                bf0[t] = bp[0];
                bf1[t] = bp[4 * 72];
            }
            #pragma unroll
            for (int s = 0; s < 2; ++s) {
                const float* ar0 = ts + (c_base + s * 16 + grp) * 68 + k0;
                const float* ar1 = ar0 + 8 * 68;
                float a0 = ar0[qd];
                float a1 = ar1[qd];
                float a2 = ar0[qd + 4];
                float a3 = ar1[qd + 4];
                #pragma unroll
                for (int t = 0; t < 8; ++t)
                    mma_tf32(acc[s][t], a0, a1, a2, a3, bf0[t], bf1[t]);
            }
        }
    }

    // Write out[b][c][j0 + j]
    float* ob = out + (size_t)b * C * HW + j0;
    #pragma unroll
    for (int s = 0; s < 2; ++s) {
        const int r0 = c_base + s * 16 + grp;
        #pragma unroll
        for (int t = 0; t < 8; ++t) {
            const int col = t * 8 + qd * 2;
            *reinterpret_cast<float2*>(ob + (size_t)r0 * HW + col) =
                make_float2(acc[s][t][0], acc[s][t][1]);
            *reinterpret_cast<float2*>(ob + (size_t)(r0 + 8) * HW + col) =
                make_float2(acc[s][t][2], acc[s][t][3]);
        }
    }
}

// ---------------------------------------------------------------------------
extern "C" void kernel_launch(void* const* d_in, const int* in_sizes, int n_in,
                              void* d_out, int out_size)
{
    const float* x    = (const float*)d_in[0];
    const float* W    = (const float*)d_in[1];
    const float* bias = (const float*)d_in[2];
    float* out        = (float*)d_out;

    const int PREP_SMEM = (C * 68 + 32 * 261 + 64) * 4;
    const int MAIN_SMEM = (64 * 260 + 64 * 260 + 256 * 68 + 64 * 72) * 4;  // 221,184 B

    cudaFuncSetAttribute(prep_kernel, cudaFuncAttributeMaxDynamicSharedMemorySize, PREP_SMEM);
    cudaFuncSetAttribute(ppm_main,    cudaFuncAttributeMaxDynamicSharedMemorySize, MAIN_SMEM);

    dim3 g1(HW / PT, BATCH);
    prep_kernel<<<g1, 256, PREP_SMEM>>>(x, W, bias);

    dim3 g2(HW / JT, BATCH);
    ppm_main<<<g2, 256, MAIN_SMEM>>>(out);
}

// round 5
// speedup vs baseline: 6.1398x; 1.9809x over previous
#include <cuda_runtime.h>
#include <cuda_fp16.h>

#define BATCH 8
#define C 256
#define HW 4096
#define JT 64     // j-tile per CTA
#define ITile 64  // i-tile
#define NT (HW / ITile)
#define PT 64     // prep pixel tile

// Scratch (half): xnT pixel-major (B, HW, C); t c-major (B, C, HW)
__device__ __half g_xnT_h[(size_t)BATCH * HW * C];
__device__ __half g_t_h  [(size_t)BATCH * C * HW];

// smem layout (halves)
#define XNJ_OFF 0
#define XNJ_STRIDE 264
#define XNI_OFF 16896              // 64*264
#define XNI_BUFSZ 16896
#define TS_OFF  50688              // XNI_OFF + 2*16896
#define TS_STRIDE 72
#define TS_BUFSZ 18432             // 256*72
#define QS_OFF  87552              // TS_OFF + 2*18432
#define QS_STRIDE 72
#define SMEM_HALVES 92160          // QS_OFF + 64*72

__device__ __forceinline__ unsigned smem_u32(const void* p) {
    unsigned a;
    asm("{ .reg .u64 t; cvta.to.shared.u64 t, %1; cvt.u32.u64 %0, t; }" : "=r"(a) : "l"(p));
    return a;
}
__device__ __forceinline__ void cpa16(unsigned dst, const void* src) {
    asm volatile("cp.async.cg.shared.global [%0], [%1], 16;" :: "r"(dst), "l"(src) : "memory");
}
__device__ __forceinline__ void cpa_commit() {
    asm volatile("cp.async.commit_group;" ::: "memory");
}
__device__ __forceinline__ void ldsm_x4(unsigned& r0, unsigned& r1, unsigned& r2, unsigned& r3,
                                        unsigned addr) {
    asm volatile("ldmatrix.sync.aligned.m8n8.x4.shared.b16 {%0,%1,%2,%3}, [%4];"
                 : "=r"(r0), "=r"(r1), "=r"(r2), "=r"(r3) : "r"(addr));
}
__device__ __forceinline__ void ldsm_x4t(unsigned& r0, unsigned& r1, unsigned& r2, unsigned& r3,
                                         unsigned addr) {
    asm volatile("ldmatrix.sync.aligned.m8n8.x4.trans.shared.b16 {%0,%1,%2,%3}, [%4];"
                 : "=r"(r0), "=r"(r1), "=r"(r2), "=r"(r3) : "r"(addr));
}
__device__ __forceinline__ void mma_f16(float d[4], unsigned a0, unsigned a1, unsigned a2,
                                        unsigned a3, unsigned b0, unsigned b1) {
    asm volatile(
        "mma.sync.aligned.m16n8k16.row.col.f32.f16.f16.f32 "
        "{%0,%1,%2,%3}, {%4,%5,%6,%7}, {%8,%9}, {%0,%1,%2,%3};"
        : "+f"(d[0]), "+f"(d[1]), "+f"(d[2]), "+f"(d[3])
        : "r"(a0), "r"(a1), "r"(a2), "r"(a3), "r"(b0), "r"(b1));
}
__device__ __forceinline__ unsigned pack_h2(float a, float b) {
    __half2 h = __floats2half2_rn(a, b);
    return *reinterpret_cast<unsigned*>(&h);
}

// ---------------------------------------------------------------------------
// Prep: normalize -> g_xnT_h (pixel-major), t = W@x + bias -> g_t_h (c-major)
// ---------------------------------------------------------------------------
__global__ void __launch_bounds__(256, 1)
prep_kernel(const float* __restrict__ x, const float* __restrict__ W,
            const float* __restrict__ bias)
{
    extern __shared__ float sm[];
    float* xs   = sm;                  // C * 68
    float* Wsm  = xs + C * 68;         // 32 * 261
    float* invn = Wsm + 32 * 261;      // 64

    const int p0  = blockIdx.x * PT;
    const int b   = blockIdx.y;
    const int tid = threadIdx.x;
    const float* xb = x + (size_t)b * C * HW;

    #pragma unroll
    for (int r = 0; r < 16; ++r) {
        int f4 = r * 256 + tid;
        int c  = f4 >> 4;
        int kq = f4 & 15;
        float4 v = *reinterpret_cast<const float4*>(xb + (size_t)c * HW + p0 + kq * 4);
        *reinterpret_cast<float4*>(xs + c * 68 + kq * 4) = v;
    }
    __syncthreads();

    if (tid < 64) {
        float s = 0.f;
        #pragma unroll 8
        for (int c = 0; c < C; ++c) { float v = xs[c * 68 + tid]; s += v * v; }
        invn[tid] = 1.0f / fmaxf(sqrtf(s), 1e-12f);
    }
    __syncthreads();

    // xnT[p][c] = x[c][p] * invn[p] -> half, pixel-major
    {
        int p   = tid & 63;
        int grp = tid >> 6;
        float inv = invn[p];
        __half* dst = g_xnT_h + ((size_t)b * HW + p0 + p) * C;
        #pragma unroll
        for (int cc = 0; cc < 16; ++cc) {
            int c = grp * 64 + cc * 4;
            uint2 u;
            u.x = pack_h2(xs[(c + 0) * 68 + p] * inv, xs[(c + 1) * 68 + p] * inv);
            u.y = pack_h2(xs[(c + 2) * 68 + p] * inv, xs[(c + 3) * 68 + p] * inv);
            *reinterpret_cast<uint2*>(dst + c) = u;
        }
    }

    // t = W @ x + bias (SIMT fp32 GEMM) -> half
    const int tx = tid & 31;
    const int ty = tid >> 5;
    float acc[8][8];
    #pragma unroll
    for (int i = 0; i < 8; ++i)
        #pragma unroll
        for (int j = 0; j < 8; ++j) acc[i][j] = 0.f;

    for (int k0 = 0; k0 < C; k0 += 32) {
        __syncthreads();
        #pragma unroll
        for (int r = 0; r < 8; ++r) {
            int f4 = r * 256 + tid;
            int o  = f4 >> 3;
            int kq = f4 & 7;
            float4 v = *reinterpret_cast<const float4*>(W + (size_t)o * C + k0 + kq * 4);
            Wsm[(kq * 4 + 0) * 261 + o] = v.x;
            Wsm[(kq * 4 + 1) * 261 + o] = v.y;
            Wsm[(kq * 4 + 2) * 261 + o] = v.z;
            Wsm[(kq * 4 + 3) * 261 + o] = v.w;
        }
        __syncthreads();
        #pragma unroll 4
        for (int kk = 0; kk < 32; ++kk) {
            float wv[8], xv[8];
            #pragma unroll
            for (int i = 0; i < 8; ++i) wv[i] = Wsm[kk * 261 + tx + 32 * i];
            #pragma unroll
            for (int j = 0; j < 8; ++j) xv[j] = xs[(k0 + kk) * 68 + ty * 8 + j];
            #pragma unroll
            for (int i = 0; i < 8; ++i)
                #pragma unroll
                for (int j = 0; j < 8; ++j)
                    acc[i][j] = fmaf(wv[i], xv[j], acc[i][j]);
        }
    }

    __half* tb = g_t_h + (size_t)b * C * HW;
    #pragma unroll
    for (int i = 0; i < 8; ++i) {
        int o = tx + 32 * i;
        float bo = __ldg(bias + o);
        #pragma unroll
        for (int j = 0; j < 8; j += 4) {
            uint2 u;
            u.x = pack_h2(acc[i][j + 0] + bo, acc[i][j + 1] + bo);
            u.y = pack_h2(acc[i][j + 2] + bo, acc[i][j + 3] + bo);
            *reinterpret_cast<uint2*>(tb + (size_t)o * HW + p0 + ty * 8 + j) = u;
        }
    }
}

// ---------------------------------------------------------------------------
// Main: fp16 mma + ldmatrix + cp.async double buffering
// ---------------------------------------------------------------------------
__global__ void __launch_bounds__(256, 1)
ppm_main(float* __restrict__ out)
{
    extern __shared__ __half smh[];
    const unsigned sbase = smem_u32(smh);

    const int j0   = blockIdx.x * JT;
    const int b    = blockIdx.y;
    const int tid  = threadIdx.x;
    const int wid  = tid >> 5;
    const int lane = tid & 31;

    // GEMM1 warp map: wm = i-strip (16 rows), wn = j-half (32 cols)
    const int wm = wid & 3;
    const int wn = wid >> 2;
    // GEMM2: warp owns c rows [wid*32, +32)
    const int c_base = wid * 32;

    const __half* xnT_b = g_xnT_h + (size_t)b * HW * C;
    const __half* t_b   = g_t_h   + (size_t)b * C * HW;

    // --- initial async loads: xnj (persistent): 64 rows x 32 chunks of 16B ---
    #pragma unroll
    for (int r = 0; r < 8; ++r) {
        int f = r * 256 + tid;
        int row = f >> 5, ch = f & 31;
        cpa16(sbase + (unsigned)((XNJ_OFF + row * XNJ_STRIDE + ch * 8) * 2),
              xnT_b + (size_t)(j0 + row) * C + ch * 8);
    }
    cpa_commit();

    auto issue_tile = [&](int it) {
        const int i0 = it * ITile;
        const unsigned xni_o = XNI_OFF + (unsigned)(it & 1) * XNI_BUFSZ;
        const unsigned ts_o  = TS_OFF  + (unsigned)(it & 1) * TS_BUFSZ;
        #pragma unroll
        for (int r = 0; r < 8; ++r) {
            int f = r * 256 + tid;
            int row = f >> 5, ch = f & 31;
            cpa16(sbase + (xni_o + (unsigned)(row * XNJ_STRIDE + ch * 8)) * 2,
                  xnT_b + (size_t)(i0 + row) * C + ch * 8);
        }
        #pragma unroll
        for (int r = 0; r < 8; ++r) {
            int f = r * 256 + tid;
            int c = f >> 3, ch = f & 7;
            cpa16(sbase + (ts_o + (unsigned)(c * TS_STRIDE + ch * 8)) * 2,
                  t_b + (size_t)c * HW + i0 + ch * 8);
        }
        cpa_commit();
    };

    issue_tile(0);

    // Persistent GEMM2 accumulators: 2 m16-strips x 8 n-tiles x 4
    float acc[2][8][4];
    #pragma unroll
    for (int s = 0; s < 2; ++s)
        #pragma unroll
        for (int t = 0; t < 8; ++t)
            #pragma unroll
            for (int r = 0; r < 4; ++r) acc[s][t][r] = 0.f;

    // Precomputed invariant address parts
    const unsigned lrow  = (unsigned)(lane & 15);
    const unsigned lkoff = (unsigned)((lane >> 4) * 8);
    // GEMM1 B: two 16-row j groups
    unsigned b1_addr[2];
    #pragma unroll
    for (int tt = 0; tt < 2; ++tt)
        b1_addr[tt] = sbase + (unsigned)((XNJ_OFF +
                      (wn * 32 + tt * 16 + lrow) * XNJ_STRIDE + lkoff) * 2);
    // GEMM2 B (trans): row = ((lane>>3)&1)*8 + (lane&7)
    const unsigned qrow = (unsigned)((((lane >> 3) & 1) * 8) + (lane & 7));

    for (int it = 0; it < NT; ++it) {
        if (it + 1 < NT) {
            issue_tile(it + 1);
            asm volatile("cp.async.wait_group 1;" ::: "memory");
        } else {
            asm volatile("cp.async.wait_group 0;" ::: "memory");
        }
        __syncthreads();

        const unsigned xni_o = XNI_OFF + (unsigned)(it & 1) * XNI_BUFSZ;
        const unsigned ts_o  = TS_OFF  + (unsigned)(it & 1) * TS_BUFSZ;

        // --- GEMM1: S (M=64 i, N=64 j, K=256), 4 n-tiles per warp ---
        float d[4][4];
        #pragma unroll
        for (int t = 0; t < 4; ++t)
            #pragma unroll
            for (int r = 0; r < 4; ++r) d[t][r] = 0.f;

        unsigned a_addr = sbase + (xni_o + (unsigned)((wm * 16 + lrow) * XNJ_STRIDE + lkoff)) * 2;
        #pragma unroll 4
        for (int kk = 0; kk < 16; ++kk) {
            unsigned a0, a1, a2, a3;
            ldsm_x4(a0, a1, a2, a3, a_addr + kk * 32);
            #pragma unroll
            for (int tt = 0; tt < 2; ++tt) {
                unsigned r0, r1, r2, r3;
                ldsm_x4(r0, r1, r2, r3, b1_addr[tt] + kk * 32);
                mma_f16(d[tt * 2 + 0], a0, a1, a2, a3, r0, r2);
                mma_f16(d[tt * 2 + 1], a0, a1, a2, a3, r1, r3);
            }
        }

        // square -> qs[i][j] (half2 stores)
        {
            __half* qsm = smh + QS_OFF;
            const int r0 = wm * 16 + (lane >> 2);
            #pragma unroll
            for (int t = 0; t < 4; ++t) {
                const int col = wn * 32 + t * 8 + (lane & 3) * 2;
                *reinterpret_cast<unsigned*>(qsm + r0 * QS_STRIDE + col) =
                    pack_h2(d[t][0] * d[t][0], d[t][1] * d[t][1]);
                *reinterpret_cast<unsigned*>(qsm + (r0 + 8) * QS_STRIDE + col) =
                    pack_h2(d[t][2] * d[t][2], d[t][3] * d[t][3]);
            }
        }
        __syncthreads();

        // --- GEMM2: out[c][j] += t[c][i] * q[i][j] (M=32/warp, N=64, K=64) ---
        #pragma unroll
        for (int kk = 0; kk < 4; ++kk) {
            const unsigned k0 = kk * 16;
            unsigned aa[2][4];
            #pragma unroll
            for (int s = 0; s < 2; ++s) {
                unsigned addr = sbase + (ts_o +
                    (unsigned)((c_base + s * 16 + lrow) * TS_STRIDE) + k0 + lkoff) * 2;
                ldsm_x4(aa[s][0], aa[s][1], aa[s][2], aa[s][3], addr);
            }
            #pragma unroll
            for (int tp = 0; tp < 4; ++tp) {
                unsigned r0, r1, r2, r3;
                unsigned addr = sbase + (unsigned)((QS_OFF +
                    (k0 + qrow) * QS_STRIDE + tp * 16) * 2) + lkoff * 2;
                ldsm_x4t(r0, r1, r2, r3, addr);
                #pragma unroll
                for (int s = 0; s < 2; ++s) {
                    mma_f16(acc[s][tp * 2 + 0], aa[s][0], aa[s][1], aa[s][2], aa[s][3], r0, r1);
                    mma_f16(acc[s][tp * 2 + 1], aa[s][0], aa[s][1], aa[s][2], aa[s][3], r2, r3);
                }
            }
        }
        __syncthreads();
    }

    // Write out[b][c][j0 + j]
    float* ob = out + (size_t)b * C * HW + j0;
    #pragma unroll
    for (int s = 0; s < 2; ++s) {
        const int r0 = c_base + s * 16 + (lane >> 2);
        #pragma unroll
        for (int t = 0; t < 8; ++t) {
            const int col = t * 8 + (lane & 3) * 2;
            *reinterpret_cast<float2*>(ob + (size_t)r0 * HW + col) =
                make_float2(acc[s][t][0], acc[s][t][1]);
            *reinterpret_cast<float2*>(ob + (size_t)(r0 + 8) * HW + col) =
                make_float2(acc[s][t][2], acc[s][t][3]);
        }
    }
}

// ---------------------------------------------------------------------------
extern "C" void kernel_launch(void* const* d_in, const int* in_sizes, int n_in,
                              void* d_out, int out_size)
{
    const float* x    = (const float*)d_in[0];
    const float* W    = (const float*)d_in[1];
    const float* bias = (const float*)d_in[2];
    float* out        = (float*)d_out;

    const int PREP_SMEM = (C * 68 + 32 * 261 + 64) * 4;
    const int MAIN_SMEM = SMEM_HALVES * 2;   // 184,320 B

    cudaFuncSetAttribute(prep_kernel, cudaFuncAttributeMaxDynamicSharedMemorySize, PREP_SMEM);
    cudaFuncSetAttribute(ppm_main,    cudaFuncAttributeMaxDynamicSharedMemorySize, MAIN_SMEM);

    dim3 g1(HW / PT, BATCH);
    prep_kernel<<<g1, 256, PREP_SMEM>>>(x, W, bias);

    dim3 g2(HW / JT, BATCH);
    ppm_main<<<g2, 256, MAIN_SMEM>>>(out);
}

// round 6
// speedup vs baseline: 7.1624x; 1.1665x over previous
#include <cuda_runtime.h>
#include <cuda_fp16.h>

#define BATCH 8
#define C 256
#define HW 4096
#define NJ 64      // j-tile per CTA
#define SS 128     // superstep: i-rows per iteration
#define NSS (HW / SS)
#define PT 64      // prep pixel tile

// Global scratch (fp16)
__device__ __half g_xnT_h[(size_t)BATCH * HW * C];  // normalized, pixel-major (p, c)
__device__ __half g_xT_h [(size_t)BATCH * HW * C];  // raw,        pixel-major (p, c)
__device__ __half g_t_h  [(size_t)BATCH * C * HW];  // t = Wx+b,   c-major (c, p)
__device__ __half g_W_h  [C * C];                   // W fp16

// main smem layout (halves)
#define XNJ_OFF 0
#define XN_ST   264
#define XNI_OFF 16896              // 64*264
#define TS0_OFF 50688              // XNI_OFF + 128*264
#define TS1_OFF 69120              // +256*72
#define TS_ST   72
#define QS_OFF  87552              // +256*72
#define QS_ST   72
#define SMEM_MAIN_H 96768          // +128*72

__device__ __forceinline__ unsigned smem_u32(const void* p) {
    unsigned a;
    asm("{ .reg .u64 t; cvta.to.shared.u64 t, %1; cvt.u32.u64 %0, t; }" : "=r"(a) : "l"(p));
    return a;
}
__device__ __forceinline__ void cpa16(unsigned dst, const void* src) {
    asm volatile("cp.async.cg.shared.global [%0], [%1], 16;" :: "r"(dst), "l"(src) : "memory");
}
__device__ __forceinline__ void cpa_commit() {
    asm volatile("cp.async.commit_group;" ::: "memory");
}
__device__ __forceinline__ void ldsm_x4(unsigned* r, unsigned addr) {
    asm volatile("ldmatrix.sync.aligned.m8n8.x4.shared.b16 {%0,%1,%2,%3}, [%4];"
                 : "=r"(r[0]), "=r"(r[1]), "=r"(r[2]), "=r"(r[3]) : "r"(addr));
}
__device__ __forceinline__ void ldsm_x4t(unsigned* r, unsigned addr) {
    asm volatile("ldmatrix.sync.aligned.m8n8.x4.trans.shared.b16 {%0,%1,%2,%3}, [%4];"
                 : "=r"(r[0]), "=r"(r[1]), "=r"(r[2]), "=r"(r[3]) : "r"(addr));
}
__device__ __forceinline__ void mma_f16(float d[4], const unsigned a[4], unsigned b0, unsigned b1) {
    asm volatile(
        "mma.sync.aligned.m16n8k16.row.col.f32.f16.f16.f32 "
        "{%0,%1,%2,%3}, {%4,%5,%6,%7}, {%8,%9}, {%0,%1,%2,%3};"
        : "+f"(d[0]), "+f"(d[1]), "+f"(d[2]), "+f"(d[3])
        : "r"(a[0]), "r"(a[1]), "r"(a[2]), "r"(a[3]), "r"(b0), "r"(b1));
}
__device__ __forceinline__ unsigned pack_h2(float a, float b) {
    __half2 h = __floats2half2_rn(a, b);
    return *reinterpret_cast<unsigned*>(&h);
}

// ---------------------------------------------------------------------------
// W fp32 -> fp16
// ---------------------------------------------------------------------------
__global__ void conv_w_kernel(const float* __restrict__ W) {
    int i = (blockIdx.x * 256 + threadIdx.x) * 4;
    float4 v = *reinterpret_cast<const float4*>(W + i);
    uint2 u;
    u.x = pack_h2(v.x, v.y);
    u.y = pack_h2(v.z, v.w);
    *reinterpret_cast<uint2*>(g_W_h + i) = u;
}

// ---------------------------------------------------------------------------
// Prep: per (b, 64-pixel tile): invn, write xnT_h (normalized) + xT_h (raw)
// ---------------------------------------------------------------------------
__global__ void __launch_bounds__(256, 1)
prep_kernel(const float* __restrict__ x)
{
    extern __shared__ float sm[];
    float* xs   = sm;                  // C * 68
    float* invn = xs + C * 68;         // 64

    const int p0  = blockIdx.x * PT;
    const int b   = blockIdx.y;
    const int tid = threadIdx.x;
    const float* xb = x + (size_t)b * C * HW;

    #pragma unroll
    for (int r = 0; r < 16; ++r) {
        int f4 = r * 256 + tid;
        int c  = f4 >> 4;
        int kq = f4 & 15;
        float4 v = *reinterpret_cast<const float4*>(xb + (size_t)c * HW + p0 + kq * 4);
        *reinterpret_cast<float4*>(xs + c * 68 + kq * 4) = v;
    }
    __syncthreads();

    if (tid < 64) {
        float s = 0.f;
        #pragma unroll 8
        for (int c = 0; c < C; ++c) { float v = xs[c * 68 + tid]; s += v * v; }
        invn[tid] = 1.0f / fmaxf(sqrtf(s), 1e-12f);
    }
    __syncthreads();

    {
        int p   = tid & 63;
        int grp = tid >> 6;
        float inv = invn[p];
        __half* dn = g_xnT_h + ((size_t)b * HW + p0 + p) * C;
        __half* dr = g_xT_h  + ((size_t)b * HW + p0 + p) * C;
        #pragma unroll
        for (int cc = 0; cc < 16; ++cc) {
            int c = grp * 64 + cc * 4;
            float v0 = xs[(c + 0) * 68 + p], v1 = xs[(c + 1) * 68 + p];
            float v2 = xs[(c + 2) * 68 + p], v3 = xs[(c + 3) * 68 + p];
            uint2 un, ur;
            un.x = pack_h2(v0 * inv, v1 * inv);
            un.y = pack_h2(v2 * inv, v3 * inv);
            ur.x = pack_h2(v0, v1);
            ur.y = pack_h2(v2, v3);
            *reinterpret_cast<uint2*>(dn + c) = un;
            *reinterpret_cast<uint2*>(dr + c) = ur;
        }
    }
}

// ---------------------------------------------------------------------------
// tgemm: t[c][p] = sum_k W[c][k] x[k][p] + bias[c]  (fp16 MMA, fp32 accum)
// Per CTA: 256 c x 128 p, K=256 in 4 chunks of 64, double-buffered.
// smem halves: Ws[2][256*72], xs[2][128*72]
// ---------------------------------------------------------------------------
#define TG_WS 18432
#define TG_XS 9216
#define TG_SMEM_H (2 * TG_WS + 2 * TG_XS)

__global__ void __launch_bounds__(256, 1)
tgemm_kernel(const float* __restrict__ bias)
{
    extern __shared__ __half smh[];
    const unsigned sbase = smem_u32(smh);

    const int p0  = blockIdx.x * 128;
    const int b   = blockIdx.y;
    const int tid = threadIdx.x;
    const int wid = tid >> 5;
    const int lane = tid & 31;
    const int wm = wid & 3;       // c-group: 64 rows
    const int wn = wid >> 2;      // p-group: 64 cols
    const unsigned lrow = (unsigned)(lane & 15);
    const unsigned lk8  = (unsigned)((lane >> 4) * 8);

    const __half* xT_b = g_xT_h + (size_t)b * HW * C;

    auto issue = [&](int ck) {
        const int k0 = ck * 64;
        const unsigned ws_o = (unsigned)((ck & 1) * TG_WS);
        const unsigned xs_o = (unsigned)(2 * TG_WS + (ck & 1) * TG_XS);
        #pragma unroll
        for (int r = 0; r < 8; ++r) {
            int f = r * 256 + tid;
            int c = f >> 3, ch = f & 7;
            cpa16(sbase + (ws_o + (unsigned)(c * TS_ST + ch * 8)) * 2,
                  g_W_h + (size_t)c * C + k0 + ch * 8);
        }
        #pragma unroll
        for (int r = 0; r < 4; ++r) {
            int f = r * 256 + tid;
            int p = f >> 3, ch = f & 7;
            cpa16(sbase + (xs_o + (unsigned)(p * TS_ST + ch * 8)) * 2,
                  xT_b + (size_t)(p0 + p) * C + k0 + ch * 8);
        }
        cpa_commit();
    };

    issue(0);

    float acc[4][8][4];
    #pragma unroll
    for (int m = 0; m < 4; ++m)
        #pragma unroll
        for (int t = 0; t < 8; ++t)
            #pragma unroll
            for (int r = 0; r < 4; ++r) acc[m][t][r] = 0.f;

    for (int ck = 0; ck < 4; ++ck) {
        if (ck + 1 < 4) {
            issue(ck + 1);
            asm volatile("cp.async.wait_group 1;" ::: "memory");
        } else {
            asm volatile("cp.async.wait_group 0;" ::: "memory");
        }
        __syncthreads();
        const unsigned ws_o = (unsigned)((ck & 1) * TG_WS);
        const unsigned xs_o = (unsigned)(2 * TG_WS + (ck & 1) * TG_XS);

        const unsigned aA = sbase + (ws_o + (unsigned)((wm * 64 + lrow) * TS_ST) + lk8) * 2;
        const unsigned aB = sbase + (xs_o + (unsigned)((wn * 64 + lrow) * TS_ST) + lk8) * 2;
        #pragma unroll
        for (int kk = 0; kk < 4; ++kk) {
            unsigned a[4][4], bb[4][4];
            #pragma unroll
            for (int m = 0; m < 4; ++m)
                ldsm_x4(a[m], aA + (unsigned)(m * 16 * TS_ST * 2) + kk * 32);
            #pragma unroll
            for (int n = 0; n < 4; ++n)
                ldsm_x4(bb[n], aB + (unsigned)(n * 16 * TS_ST * 2) + kk * 32);
            #pragma unroll
            for (int m = 0; m < 4; ++m)
                #pragma unroll
                for (int n = 0; n < 4; ++n) {
                    mma_f16(acc[m][n * 2 + 0], a[m], bb[n][0], bb[n][2]);
                    mma_f16(acc[m][n * 2 + 1], a[m], bb[n][1], bb[n][3]);
                }
        }
        __syncthreads();
    }

    __half* tb = g_t_h + (size_t)b * C * HW;
    #pragma unroll
    for (int m = 0; m < 4; ++m) {
        const int c0 = wm * 64 + m * 16 + (lane >> 2);
        const float bo0 = __ldg(bias + c0);
        const float bo1 = __ldg(bias + c0 + 8);
        #pragma unroll
        for (int t = 0; t < 8; ++t) {
            const int p = p0 + wn * 64 + t * 8 + (lane & 3) * 2;
            *reinterpret_cast<unsigned*>(tb + (size_t)c0 * HW + p) =
                pack_h2(acc[m][t][0] + bo0, acc[m][t][1] + bo0);
            *reinterpret_cast<unsigned*>(tb + (size_t)(c0 + 8) * HW + p) =
                pack_h2(acc[m][t][2] + bo1, acc[m][t][3] + bo1);
        }
    }
}

// ---------------------------------------------------------------------------
// Main: per (b, 64-j tile); superstep of 128 i-rows.
// ---------------------------------------------------------------------------
__global__ void __launch_bounds__(256, 1)
ppm_main(float* __restrict__ out)
{
    extern __shared__ __half smh[];
    const unsigned sbase = smem_u32(smh);

    const int j0   = blockIdx.x * NJ;
    const int b    = blockIdx.y;
    const int tid  = threadIdx.x;
    const int wid  = tid >> 5;
    const int lane = tid & 31;

    const int wm = wid & 3;       // GEMM1: i-strip (32 rows)
    const int wn = wid >> 2;      // GEMM1: j-half (32 cols)
    const int c_base = wid * 32;  // GEMM2: c rows

    const unsigned lrow = (unsigned)(lane & 15);
    const unsigned lk8  = (unsigned)((lane >> 4) * 8);
    const unsigned qrow = (unsigned)((((lane >> 3) & 1) * 8) + (lane & 7));

    const __half* xnT_b = g_xnT_h + (size_t)b * HW * C;
    const __half* t_b   = g_t_h   + (size_t)b * C * HW;

    // xnj persistent: 64 rows x 32 chunks
    #pragma unroll
    for (int r = 0; r < 8; ++r) {
        int f = r * 256 + tid;
        int row = f >> 5, ch = f & 31;
        cpa16(sbase + (unsigned)((XNJ_OFF + row * XN_ST + ch * 8) * 2),
              xnT_b + (size_t)(j0 + row) * C + ch * 8);
    }
    auto issue_xni = [&](int s) {
        const int i0 = s * SS;
        #pragma unroll
        for (int r = 0; r < 16; ++r) {
            int f = r * 256 + tid;
            int row = f >> 5, ch = f & 31;
            cpa16(sbase + (unsigned)((XNI_OFF + row * XN_ST + ch * 8) * 2),
                  xnT_b + (size_t)(i0 + row) * C + ch * 8);
        }
        cpa_commit();
    };
    auto issue_ts = [&](unsigned tso, int kbase) {
        #pragma unroll
        for (int r = 0; r < 8; ++r) {
            int f = r * 256 + tid;
            int c = f >> 3, ch = f & 7;
            cpa16(sbase + (tso + (unsigned)(c * TS_ST + ch * 8)) * 2,
                  t_b + (size_t)c * HW + kbase + ch * 8);
        }
        cpa_commit();
    };

    issue_xni(0);
    issue_ts(TS0_OFF, 0);
    issue_ts(TS1_OFF, 64);

    float acc[2][8][4];
    #pragma unroll
    for (int s = 0; s < 2; ++s)
        #pragma unroll
        for (int t = 0; t < 8; ++t)
            #pragma unroll
            for (int r = 0; r < 4; ++r) acc[s][t][r] = 0.f;

    // invariant addresses
    const unsigned aA0 = sbase + (unsigned)((XNI_OFF + (wm * 32 + lrow) * XN_ST) + lk8) * 2;
    const unsigned aB0 = sbase + (unsigned)((XNJ_OFF + (wn * 32 + lrow) * XN_ST) + lk8) * 2;

    for (int s = 0; s < NSS; ++s) {
        asm volatile("cp.async.wait_group 0;" ::: "memory");
        __syncthreads();   // xni(s), ts0(s), ts1(s) ready; qs free

        // --- GEMM1: S[128 i][64 j], K=256; warp tile 32x32 ---
        float d[2][4][4];
        #pragma unroll
        for (int m = 0; m < 2; ++m)
            #pragma unroll
            for (int t = 0; t < 4; ++t)
                #pragma unroll
                for (int r = 0; r < 4; ++r) d[m][t][r] = 0.f;

        #pragma unroll 4
        for (int kk = 0; kk < 16; ++kk) {
            unsigned a[2][4], b0[4], b1[4];
            ldsm_x4(a[0], aA0 + kk * 32);
            ldsm_x4(a[1], aA0 + 16 * XN_ST * 2 + kk * 32);
            ldsm_x4(b0, aB0 + kk * 32);
            ldsm_x4(b1, aB0 + 16 * XN_ST * 2 + kk * 32);
            #pragma unroll
            for (int m = 0; m < 2; ++m) {
                mma_f16(d[m][0], a[m], b0[0], b0[2]);
                mma_f16(d[m][1], a[m], b0[1], b0[3]);
                mma_f16(d[m][2], a[m], b1[0], b1[2]);
                mma_f16(d[m][3], a[m], b1[1], b1[3]);
            }
        }

        // square -> qs[i_local][j]
        {
            __half* qsm = smh + QS_OFF;
            #pragma unroll
            for (int m = 0; m < 2; ++m) {
                const int r0 = wm * 32 + m * 16 + (lane >> 2);
                #pragma unroll
                for (int t = 0; t < 4; ++t) {
                    const int col = wn * 32 + t * 8 + (lane & 3) * 2;
                    *reinterpret_cast<unsigned*>(qsm + r0 * QS_ST + col) =
                        pack_h2(d[m][t][0] * d[m][t][0], d[m][t][1] * d[m][t][1]);
                    *reinterpret_cast<unsigned*>(qsm + (r0 + 8) * QS_ST + col) =
                        pack_h2(d[m][t][2] * d[m][t][2], d[m][t][3] * d[m][t][3]);
                }
            }
        }
        __syncthreads();   // qs visible; xni fully consumed

        if (s + 1 < NSS) issue_xni(s + 1);

        // --- GEMM2 pass A: k rows 0..63 of superstep (ts0) ---
        #pragma unroll
        for (int kk = 0; kk < 4; ++kk) {
            unsigned aa[2][4];
            unsigned addr = sbase + (TS0_OFF + (unsigned)((c_base + lrow) * TS_ST) +
                                     (unsigned)(kk * 16) + lk8) * 2;
            ldsm_x4(aa[0], addr);
            ldsm_x4(aa[1], addr + 16 * TS_ST * 2);
            #pragma unroll
            for (int tp = 0; tp < 4; ++tp) {
                unsigned bq[4];
                ldsm_x4t(bq, sbase + (unsigned)((QS_OFF + (kk * 16 + qrow) * QS_ST +
                                                 tp * 16) * 2) + lk8 * 2);
                #pragma unroll
                for (int st = 0; st < 2; ++st) {
                    mma_f16(acc[st][tp * 2 + 0], aa[st], bq[0], bq[1]);
                    mma_f16(acc[st][tp * 2 + 1], aa[st], bq[2], bq[3]);
                }
            }
        }
        __syncthreads();   // ts0 consumed
        if (s + 1 < NSS) issue_ts(TS0_OFF, (s + 1) * SS);

        // --- GEMM2 pass B: k rows 64..127 (ts1) ---
        #pragma unroll
        for (int kk = 0; kk < 4; ++kk) {
            unsigned aa[2][4];
            unsigned addr = sbase + (TS1_OFF + (unsigned)((c_base + lrow) * TS_ST) +
                                     (unsigned)(kk * 16) + lk8) * 2;
            ldsm_x4(aa[0], addr);
            ldsm_x4(aa[1], addr + 16 * TS_ST * 2);
            #pragma unroll
            for (int tp = 0; tp < 4; ++tp) {
                unsigned bq[4];
                ldsm_x4t(bq, sbase + (unsigned)((QS_OFF + (64 + kk * 16 + qrow) * QS_ST +
                                                 tp * 16) * 2) + lk8 * 2);
                #pragma unroll
                for (int st = 0; st < 2; ++st) {
                    mma_f16(acc[st][tp * 2 + 0], aa[st], bq[0], bq[1]);
                    mma_f16(acc[st][tp * 2 + 1], aa[st], bq[2], bq[3]);
                }
            }
        }
        __syncthreads();   // ts1 consumed
        if (s + 1 < NSS) issue_ts(TS1_OFF, (s + 1) * SS + 64);
    }

    // Write out[b][c][j0 + j]
    float* ob = out + (size_t)b * C * HW + j0;
    #pragma unroll
    for (int st = 0; st < 2; ++st) {
        const int r0 = c_base + st * 16 + (lane >> 2);
        #pragma unroll
        for (int t = 0; t < 8; ++t) {
            const int col = t * 8 + (lane & 3) * 2;
            *reinterpret_cast<float2*>(ob + (size_t)r0 * HW + col) =
                make_float2(acc[st][t][0], acc[st][t][1]);
            *reinterpret_cast<float2*>(ob + (size_t)(r0 + 8) * HW + col) =
                make_float2(acc[st][t][2], acc[st][t][3]);
        }
    }
}

// ---------------------------------------------------------------------------
extern "C" void kernel_launch(void* const* d_in, const int* in_sizes, int n_in,
                              void* d_out, int out_size)
{
    const float* x    = (const float*)d_in[0];
    const float* W    = (const float*)d_in[1];
    const float* bias = (const float*)d_in[2];
    float* out        = (float*)d_out;

    const int PREP_SMEM = (C * 68 + 64) * 4;
    const int TG_SMEM   = TG_SMEM_H * 2;        // 110,592 B
    const int MAIN_SMEM = SMEM_MAIN_H * 2;      // 193,536 B

    cudaFuncSetAttribute(prep_kernel,  cudaFuncAttributeMaxDynamicSharedMemorySize, PREP_SMEM);
    cudaFuncSetAttribute(tgemm_kernel, cudaFuncAttributeMaxDynamicSharedMemorySize, TG_SMEM);
    cudaFuncSetAttribute(ppm_main,     cudaFuncAttributeMaxDynamicSharedMemorySize, MAIN_SMEM);

    conv_w_kernel<<<64, 256>>>(W);

    dim3 g1(HW / PT, BATCH);
    prep_kernel<<<g1, 256, PREP_SMEM>>>(x);

    dim3 gt(HW / 128, BATCH);
    tgemm_kernel<<<gt, 256, TG_SMEM>>>(bias);

    dim3 g2(HW / NJ, BATCH);
    ppm_main<<<g2, 256, MAIN_SMEM>>>(out);
}

// round 7
// speedup vs baseline: 8.0536x; 1.1244x over previous
#include <cuda_runtime.h>
#include <cuda_fp16.h>

#define BATCH 8
#define C 256
#define HW 4096
#define NJ 64      // j-tile per CTA
#define SS 64      // superstep: i-rows per iteration
#define NSS (HW / SS)
#define PT 64      // prep pixel tile

// Global scratch (fp16)
__device__ __half g_xnT_h[(size_t)BATCH * HW * C];  // normalized, pixel-major (p, c)
__device__ __half g_xT_h [(size_t)BATCH * HW * C];  // raw,        pixel-major (p, c)
__device__ __half g_t_h  [(size_t)BATCH * C * HW];  // t = Wx+b,   c-major (c, p)
__device__ __half g_W_h  [C * C];                   // W fp16

// main smem layout (halves) — total 56,832 halves = 113,664 B (2 CTAs/SM)
#define XNJ_OFF 0
#define XN_ST   264
#define XNI_OFF 16896              // 64*264
#define TS_OFF  33792              // + 64*264
#define TS_ST   72
#define QS_OFF  52224              // + 256*72
#define QS_ST   72
#define SMEM_MAIN_H 56832          // + 64*72

__device__ __forceinline__ unsigned smem_u32(const void* p) {
    unsigned a;
    asm("{ .reg .u64 t; cvta.to.shared.u64 t, %1; cvt.u32.u64 %0, t; }" : "=r"(a) : "l"(p));
    return a;
}
__device__ __forceinline__ void cpa16(unsigned dst, const void* src) {
    asm volatile("cp.async.cg.shared.global [%0], [%1], 16;" :: "r"(dst), "l"(src) : "memory");
}
__device__ __forceinline__ void cpa_commit() {
    asm volatile("cp.async.commit_group;" ::: "memory");
}
__device__ __forceinline__ void ldsm_x4(unsigned* r, unsigned addr) {
    asm volatile("ldmatrix.sync.aligned.m8n8.x4.shared.b16 {%0,%1,%2,%3}, [%4];"
                 : "=r"(r[0]), "=r"(r[1]), "=r"(r[2]), "=r"(r[3]) : "r"(addr));
}
__device__ __forceinline__ void ldsm_x4t(unsigned* r, unsigned addr) {
    asm volatile("ldmatrix.sync.aligned.m8n8.x4.trans.shared.b16 {%0,%1,%2,%3}, [%4];"
                 : "=r"(r[0]), "=r"(r[1]), "=r"(r[2]), "=r"(r[3]) : "r"(addr));
}
__device__ __forceinline__ void mma_f16(float d[4], const unsigned a[4], unsigned b0, unsigned b1) {
    asm volatile(
        "mma.sync.aligned.m16n8k16.row.col.f32.f16.f16.f32 "
        "{%0,%1,%2,%3}, {%4,%5,%6,%7}, {%8,%9}, {%0,%1,%2,%3};"
        : "+f"(d[0]), "+f"(d[1]), "+f"(d[2]), "+f"(d[3])
        : "r"(a[0]), "r"(a[1]), "r"(a[2]), "r"(a[3]), "r"(b0), "r"(b1));
}
__device__ __forceinline__ unsigned pack_h2(float a, float b) {
    __half2 h = __floats2half2_rn(a, b);
    return *reinterpret_cast<unsigned*>(&h);
}

// ---------------------------------------------------------------------------
__global__ void conv_w_kernel(const float* __restrict__ W) {
    int i = (blockIdx.x * 256 + threadIdx.x) * 4;
    float4 v = *reinterpret_cast<const float4*>(W + i);
    uint2 u;
    u.x = pack_h2(v.x, v.y);
    u.y = pack_h2(v.z, v.w);
    *reinterpret_cast<uint2*>(g_W_h + i) = u;
}

// ---------------------------------------------------------------------------
// Prep: per (b, 64-pixel tile): invn, write xnT_h (normalized) + xT_h (raw)
// ---------------------------------------------------------------------------
__global__ void __launch_bounds__(256, 1)
prep_kernel(const float* __restrict__ x)
{
    extern __shared__ float sm[];
    float* xs   = sm;                  // C * 68
    float* invn = xs + C * 68;         // 64

    const int p0  = blockIdx.x * PT;
    const int b   = blockIdx.y;
    const int tid = threadIdx.x;
    const float* xb = x + (size_t)b * C * HW;

    #pragma unroll
    for (int r = 0; r < 16; ++r) {
        int f4 = r * 256 + tid;
        int c  = f4 >> 4;
        int kq = f4 & 15;
        float4 v = *reinterpret_cast<const float4*>(xb + (size_t)c * HW + p0 + kq * 4);
        *reinterpret_cast<float4*>(xs + c * 68 + kq * 4) = v;
    }
    __syncthreads();

    if (tid < 64) {
        float s = 0.f;
        #pragma unroll 8
        for (int c = 0; c < C; ++c) { float v = xs[c * 68 + tid]; s += v * v; }
        invn[tid] = 1.0f / fmaxf(sqrtf(s), 1e-12f);
    }
    __syncthreads();

    {
        int p   = tid & 63;
        int grp = tid >> 6;
        float inv = invn[p];
        __half* dn = g_xnT_h + ((size_t)b * HW + p0 + p) * C;
        __half* dr = g_xT_h  + ((size_t)b * HW + p0 + p) * C;
        #pragma unroll
        for (int cc = 0; cc < 16; ++cc) {
            int c = grp * 64 + cc * 4;
            float v0 = xs[(c + 0) * 68 + p], v1 = xs[(c + 1) * 68 + p];
            float v2 = xs[(c + 2) * 68 + p], v3 = xs[(c + 3) * 68 + p];
            uint2 un, ur;
            un.x = pack_h2(v0 * inv, v1 * inv);
            un.y = pack_h2(v2 * inv, v3 * inv);
            ur.x = pack_h2(v0, v1);
            ur.y = pack_h2(v2, v3);
            *reinterpret_cast<uint2*>(dn + c) = un;
            *reinterpret_cast<uint2*>(dr + c) = ur;
        }
    }
}

// ---------------------------------------------------------------------------
// tgemm: t[c][p] = sum_k W[c][k] x[k][p] + bias[c]  (fp16 MMA, fp32 accum)
// ---------------------------------------------------------------------------
#define TG_WS 18432
#define TG_XS 9216
#define TG_SMEM_H (2 * TG_WS + 2 * TG_XS)

__global__ void __launch_bounds__(256, 1)
tgemm_kernel(const float* __restrict__ bias)
{
    extern __shared__ __half smh[];
    const unsigned sbase = smem_u32(smh);

    const int p0  = blockIdx.x * 128;
    const int b   = blockIdx.y;
    const int tid = threadIdx.x;
    const int wid = tid >> 5;
    const int lane = tid & 31;
    const int wm = wid & 3;
    const int wn = wid >> 2;
    const unsigned lrow = (unsigned)(lane & 15);
    const unsigned lk8  = (unsigned)((lane >> 4) * 8);

    const __half* xT_b = g_xT_h + (size_t)b * HW * C;

    auto issue = [&](int ck) {
        const int k0 = ck * 64;
        const unsigned ws_o = (unsigned)((ck & 1) * TG_WS);
        const unsigned xs_o = (unsigned)(2 * TG_WS + (ck & 1) * TG_XS);
        #pragma unroll
        for (int r = 0; r < 8; ++r) {
            int f = r * 256 + tid;
            int c = f >> 3, ch = f & 7;
            cpa16(sbase + (ws_o + (unsigned)(c * 72 + ch * 8)) * 2,
                  g_W_h + (size_t)c * C + k0 + ch * 8);
        }
        #pragma unroll
        for (int r = 0; r < 4; ++r) {
            int f = r * 256 + tid;
            int p = f >> 3, ch = f & 7;
            cpa16(sbase + (xs_o + (unsigned)(p * 72 + ch * 8)) * 2,
                  xT_b + (size_t)(p0 + p) * C + k0 + ch * 8);
        }
        cpa_commit();
    };

    issue(0);

    float acc[4][8][4];
    #pragma unroll
    for (int m = 0; m < 4; ++m)
        #pragma unroll
        for (int t = 0; t < 8; ++t)
            #pragma unroll
            for (int r = 0; r < 4; ++r) acc[m][t][r] = 0.f;

    for (int ck = 0; ck < 4; ++ck) {
        if (ck + 1 < 4) {
            issue(ck + 1);
            asm volatile("cp.async.wait_group 1;" ::: "memory");
        } else {
            asm volatile("cp.async.wait_group 0;" ::: "memory");
        }
        __syncthreads();
        const unsigned ws_o = (unsigned)((ck & 1) * TG_WS);
        const unsigned xs_o = (unsigned)(2 * TG_WS + (ck & 1) * TG_XS);

        const unsigned aA = sbase + (ws_o + (unsigned)((wm * 64 + lrow) * 72) + lk8) * 2;
        const unsigned aB = sbase + (xs_o + (unsigned)((wn * 64 + lrow) * 72) + lk8) * 2;
        #pragma unroll
        for (int kk = 0; kk < 4; ++kk) {
            unsigned a[4][4], bb[4][4];
            #pragma unroll
            for (int m = 0; m < 4; ++m)
                ldsm_x4(a[m], aA + (unsigned)(m * 16 * 72 * 2) + kk * 32);
            #pragma unroll
            for (int n = 0; n < 4; ++n)
                ldsm_x4(bb[n], aB + (unsigned)(n * 16 * 72 * 2) + kk * 32);
            #pragma unroll
            for (int m = 0; m < 4; ++m)
                #pragma unroll
                for (int n = 0; n < 4; ++n) {
                    mma_f16(acc[m][n * 2 + 0], a[m], bb[n][0], bb[n][2]);
                    mma_f16(acc[m][n * 2 + 1], a[m], bb[n][1], bb[n][3]);
                }
        }
        __syncthreads();
    }

    __half* tb = g_t_h + (size_t)b * C * HW;
    #pragma unroll
    for (int m = 0; m < 4; ++m) {
        const int c0 = wm * 64 + m * 16 + (lane >> 2);
        const float bo0 = __ldg(bias + c0);
        const float bo1 = __ldg(bias + c0 + 8);
        #pragma unroll
        for (int t = 0; t < 8; ++t) {
            const int p = p0 + wn * 64 + t * 8 + (lane & 3) * 2;
            *reinterpret_cast<unsigned*>(tb + (size_t)c0 * HW + p) =
                pack_h2(acc[m][t][0] + bo0, acc[m][t][1] + bo0);
            *reinterpret_cast<unsigned*>(tb + (size_t)(c0 + 8) * HW + p) =
                pack_h2(acc[m][t][2] + bo1, acc[m][t][3] + bo1);
        }
    }
}

// ---------------------------------------------------------------------------
// Main: per (b, 64-j tile); superstep of 64 i-rows; 2 CTAs/SM.
// ---------------------------------------------------------------------------
__global__ void __launch_bounds__(256, 2)
ppm_main(float* __restrict__ out)
{
    extern __shared__ __half smh[];
    const unsigned sbase = smem_u32(smh);

    const int j0   = blockIdx.x * NJ;
    const int b    = blockIdx.y;
    const int tid  = threadIdx.x;
    const int wid  = tid >> 5;
    const int lane = tid & 31;

    const int wm = wid & 1;       // GEMM1: i-strip (32 rows)
    const int wn = wid >> 1;      // GEMM1: j-strip (16 cols)
    const int c_base = wid * 32;  // GEMM2: c rows

    const unsigned lrow = (unsigned)(lane & 15);
    const unsigned lk8  = (unsigned)((lane >> 4) * 8);
    const unsigned qrow = (unsigned)((((lane >> 3) & 1) * 8) + (lane & 7));

    const __half* xnT_b = g_xnT_h + (size_t)b * HW * C;
    const __half* t_b   = g_t_h   + (size_t)b * C * HW;

    // xnj persistent: 64 rows x 32 chunks of 16B
    #pragma unroll
    for (int r = 0; r < 8; ++r) {
        int f = r * 256 + tid;
        int row = f >> 5, ch = f & 31;
        cpa16(sbase + (unsigned)((XNJ_OFF + row * XN_ST + ch * 8) * 2),
              xnT_b + (size_t)(j0 + row) * C + ch * 8);
    }
    auto issue_xni = [&](int s) {
        const int i0 = s * SS;
        #pragma unroll
        for (int r = 0; r < 8; ++r) {
            int f = r * 256 + tid;
            int row = f >> 5, ch = f & 31;
            cpa16(sbase + (unsigned)((XNI_OFF + row * XN_ST + ch * 8) * 2),
                  xnT_b + (size_t)(i0 + row) * C + ch * 8);
        }
        cpa_commit();
    };
    auto issue_ts = [&](int s) {
        const int i0 = s * SS;
        #pragma unroll
        for (int r = 0; r < 8; ++r) {
            int f = r * 256 + tid;
            int c = f >> 3, ch = f & 7;
            cpa16(sbase + (unsigned)((TS_OFF + c * TS_ST + ch * 8) * 2),
                  t_b + (size_t)c * HW + i0 + ch * 8);
        }
        cpa_commit();
    };

    issue_xni(0);
    issue_ts(0);

    float acc[2][8][4];
    #pragma unroll
    for (int s = 0; s < 2; ++s)
        #pragma unroll
        for (int t = 0; t < 8; ++t)
            #pragma unroll
            for (int r = 0; r < 4; ++r) acc[s][t][r] = 0.f;

    const unsigned aA0 = sbase + (unsigned)((XNI_OFF + (wm * 32 + lrow) * XN_ST) + lk8) * 2;
    const unsigned aB0 = sbase + (unsigned)((XNJ_OFF + (wn * 16 + lrow) * XN_ST) + lk8) * 2;

    for (int s = 0; s < NSS; ++s) {
        asm volatile("cp.async.wait_group 0;" ::: "memory");
        __syncthreads();   // xni(s), ts(s) ready; qs free (all warps past GEMM2(s-1))

        // --- GEMM1: S[64 i][64 j], K=256; warp tile 32x16 ---
        float d[2][2][4];
        #pragma unroll
        for (int m = 0; m < 2; ++m)
            #pragma unroll
            for (int t = 0; t < 2; ++t)
                #pragma unroll
                for (int r = 0; r < 4; ++r) d[m][t][r] = 0.f;

        #pragma unroll 4
        for (int kk = 0; kk < 16; ++kk) {
            unsigned a[2][4], b0[4];
            ldsm_x4(a[0], aA0 + kk * 32);
            ldsm_x4(a[1], aA0 + 16 * XN_ST * 2 + kk * 32);
            ldsm_x4(b0, aB0 + kk * 32);
            #pragma unroll
            for (int m = 0; m < 2; ++m) {
                mma_f16(d[m][0], a[m], b0[0], b0[2]);
                mma_f16(d[m][1], a[m], b0[1], b0[3]);
            }
        }

        // square -> qs[i_local][j]
        {
            __half* qsm = smh + QS_OFF;
            #pragma unroll
            for (int m = 0; m < 2; ++m) {
                const int r0 = wm * 32 + m * 16 + (lane >> 2);
                #pragma unroll
                for (int t = 0; t < 2; ++t) {
                    const int col = wn * 16 + t * 8 + (lane & 3) * 2;
                    *reinterpret_cast<unsigned*>(qsm + r0 * QS_ST + col) =
                        pack_h2(d[m][t][0] * d[m][t][0], d[m][t][1] * d[m][t][1]);
                    *reinterpret_cast<unsigned*>(qsm + (r0 + 8) * QS_ST + col) =
                        pack_h2(d[m][t][2] * d[m][t][2], d[m][t][3] * d[m][t][3]);
                }
            }
        }
        __syncthreads();   // qs visible; xni fully consumed

        if (s + 1 < NSS) issue_xni(s + 1);   // overlaps with GEMM2

        // --- GEMM2: out[c][j] += t[c][i] * q[i][j] (32c/warp x 64j, K=64) ---
        #pragma unroll
        for (int kk = 0; kk < 4; ++kk) {
            unsigned aa[2][4];
            unsigned addr = sbase + (TS_OFF + (unsigned)((c_base + lrow) * TS_ST) +
                                     (unsigned)(kk * 16) + lk8) * 2;
            ldsm_x4(aa[0], addr);
            ldsm_x4(aa[1], addr + 16 * TS_ST * 2);
            #pragma unroll
            for (int tp = 0; tp < 4; ++tp) {
                unsigned bq[4];
                ldsm_x4t(bq, sbase + (unsigned)((QS_OFF + (kk * 16 + qrow) * QS_ST +
                                                 tp * 16) * 2) + lk8 * 2);
                #pragma unroll
                for (int st = 0; st < 2; ++st) {
                    mma_f16(acc[st][tp * 2 + 0], aa[st], bq[0], bq[1]);
                    mma_f16(acc[st][tp * 2 + 1], aa[st], bq[2], bq[3]);
                }
            }
        }
        __syncthreads();   // ts consumed
        if (s + 1 < NSS) issue_ts(s + 1);
    }

    // Write out[b][c][j0 + j]
    float* ob = out + (size_t)b * C * HW + j0;
    #pragma unroll
    for (int st = 0; st < 2; ++st) {
        const int r0 = c_base + st * 16 + (lane >> 2);
        #pragma unroll
        for (int t = 0; t < 8; ++t) {
            const int col = t * 8 + (lane & 3) * 2;
            *reinterpret_cast<float2*>(ob + (size_t)r0 * HW + col) =
                make_float2(acc[st][t][0], acc[st][t][1]);
            *reinterpret_cast<float2*>(ob + (size_t)(r0 + 8) * HW + col) =
                make_float2(acc[st][t][2], acc[st][t][3]);
        }
    }
}

// ---------------------------------------------------------------------------
extern "C" void kernel_launch(void* const* d_in, const int* in_sizes, int n_in,
                              void* d_out, int out_size)
{
    const float* x    = (const float*)d_in[0];
    const float* W    = (const float*)d_in[1];
    const float* bias = (const float*)d_in[2];
    float* out        = (float*)d_out;

    const int PREP_SMEM = (C * 68 + 64) * 4;
    const int TG_SMEM   = TG_SMEM_H * 2;        // 110,592 B
    const int MAIN_SMEM = SMEM_MAIN_H * 2;      // 113,664 B -> 2 CTAs/SM

    cudaFuncSetAttribute(prep_kernel,  cudaFuncAttributeMaxDynamicSharedMemorySize, PREP_SMEM);
    cudaFuncSetAttribute(tgemm_kernel, cudaFuncAttributeMaxDynamicSharedMemorySize, TG_SMEM);
    cudaFuncSetAttribute(ppm_main,     cudaFuncAttributeMaxDynamicSharedMemorySize, MAIN_SMEM);

    conv_w_kernel<<<64, 256>>>(W);

    dim3 g1(HW / PT, BATCH);
    prep_kernel<<<g1, 256, PREP_SMEM>>>(x);

    dim3 gt(HW / 128, BATCH);
    tgemm_kernel<<<gt, 256, TG_SMEM>>>(bias);

    dim3 g2(HW / NJ, BATCH);
    ppm_main<<<g2, 256, MAIN_SMEM>>>(out);
}

// round 8
// speedup vs baseline: 9.4423x; 1.1724x over previous
#include <cuda_runtime.h>
#include <cuda_fp16.h>

#define BATCH 8
#define C 256
#define HW 4096
#define PT 64
#define TI 128
#define NTI (HW / TI)              // 32
#define NPAIR (NTI * (NTI + 1) / 2)  // 528

// Global scratch (fp16)
__device__ __half g_xnT_h[(size_t)BATCH * HW * C];  // normalized, pixel-major (p, c)
__device__ __half g_xT_h [(size_t)BATCH * HW * C];  // raw,        pixel-major (p, c)
__device__ __half g_t_h  [(size_t)BATCH * C * HW];  // t = Wx+b,   c-major (c, p)
__device__ __half g_W_h  [C * C];                   // W fp16
__device__ __half g_Q    [(size_t)BATCH * HW * HW]; // Q = S^2, lower-block-triangle only

__device__ __forceinline__ unsigned smem_u32(const void* p) {
    unsigned a;
    asm("{ .reg .u64 t; cvta.to.shared.u64 t, %1; cvt.u32.u64 %0, t; }" : "=r"(a) : "l"(p));
    return a;
}
__device__ __forceinline__ void cpa16(unsigned dst, const void* src) {
    asm volatile("cp.async.cg.shared.global [%0], [%1], 16;" :: "r"(dst), "l"(src) : "memory");
}
__device__ __forceinline__ void cpa_commit() {
    asm volatile("cp.async.commit_group;" ::: "memory");
}
__device__ __forceinline__ void ldsm_x4(unsigned* r, unsigned addr) {
    asm volatile("ldmatrix.sync.aligned.m8n8.x4.shared.b16 {%0,%1,%2,%3}, [%4];"
                 : "=r"(r[0]), "=r"(r[1]), "=r"(r[2]), "=r"(r[3]) : "r"(addr));
}
__device__ __forceinline__ void ldsm_x4t(unsigned* r, unsigned addr) {
    asm volatile("ldmatrix.sync.aligned.m8n8.x4.trans.shared.b16 {%0,%1,%2,%3}, [%4];"
                 : "=r"(r[0]), "=r"(r[1]), "=r"(r[2]), "=r"(r[3]) : "r"(addr));
}
__device__ __forceinline__ void mma_f16(float d[4], const unsigned a[4], unsigned b0, unsigned b1) {
    asm volatile(
        "mma.sync.aligned.m16n8k16.row.col.f32.f16.f16.f32 "
        "{%0,%1,%2,%3}, {%4,%5,%6,%7}, {%8,%9}, {%0,%1,%2,%3};"
        : "+f"(d[0]), "+f"(d[1]), "+f"(d[2]), "+f"(d[3])
        : "r"(a[0]), "r"(a[1]), "r"(a[2]), "r"(a[3]), "r"(b0), "r"(b1));
}
__device__ __forceinline__ unsigned pack_h2(float a, float b) {
    __half2 h = __floats2half2_rn(a, b);
    return *reinterpret_cast<unsigned*>(&h);
}

// ---------------------------------------------------------------------------
__global__ void conv_w_kernel(const float* __restrict__ W) {
    int i = (blockIdx.x * 256 + threadIdx.x) * 4;
    float4 v = *reinterpret_cast<const float4*>(W + i);
    uint2 u;
    u.x = pack_h2(v.x, v.y);
    u.y = pack_h2(v.z, v.w);
    *reinterpret_cast<uint2*>(g_W_h + i) = u;
}

// ---------------------------------------------------------------------------
// Prep: per (b, 64-pixel tile): invn, write xnT_h (normalized) + xT_h (raw)
// ---------------------------------------------------------------------------
__global__ void __launch_bounds__(256, 1)
prep_kernel(const float* __restrict__ x)
{
    extern __shared__ float sm[];
    float* xs   = sm;                  // C * 68
    float* invn = xs + C * 68;         // 64

    const int p0  = blockIdx.x * PT;
    const int b   = blockIdx.y;
    const int tid = threadIdx.x;
    const float* xb = x + (size_t)b * C * HW;

    #pragma unroll
    for (int r = 0; r < 16; ++r) {
        int f4 = r * 256 + tid;
        int c  = f4 >> 4;
        int kq = f4 & 15;
        float4 v = *reinterpret_cast<const float4*>(xb + (size_t)c * HW + p0 + kq * 4);
        *reinterpret_cast<float4*>(xs + c * 68 + kq * 4) = v;
    }
    __syncthreads();

    if (tid < 64) {
        float s = 0.f;
        #pragma unroll 8
        for (int c = 0; c < C; ++c) { float v = xs[c * 68 + tid]; s += v * v; }
        invn[tid] = 1.0f / fmaxf(sqrtf(s), 1e-12f);
    }
    __syncthreads();

    {
        int p   = tid & 63;
        int grp = tid >> 6;
        float inv = invn[p];
        __half* dn = g_xnT_h + ((size_t)b * HW + p0 + p) * C;
        __half* dr = g_xT_h  + ((size_t)b * HW + p0 + p) * C;
        #pragma unroll
        for (int cc = 0; cc < 16; ++cc) {
            int c = grp * 64 + cc * 4;
            float v0 = xs[(c + 0) * 68 + p], v1 = xs[(c + 1) * 68 + p];
            float v2 = xs[(c + 2) * 68 + p], v3 = xs[(c + 3) * 68 + p];
            uint2 un, ur;
            un.x = pack_h2(v0 * inv, v1 * inv);
            un.y = pack_h2(v2 * inv, v3 * inv);
            ur.x = pack_h2(v0, v1);
            ur.y = pack_h2(v2, v3);
            *reinterpret_cast<uint2*>(dn + c) = un;
            *reinterpret_cast<uint2*>(dr + c) = ur;
        }
    }
}

// ---------------------------------------------------------------------------
// tgemm: t[c][p] = sum_k W[c][k] x[k][p] + bias[c]
// ---------------------------------------------------------------------------
#define TG_WS 18432
#define TG_XS 9216
#define TG_SMEM_H (2 * TG_WS + 2 * TG_XS)

__global__ void __launch_bounds__(256, 1)
tgemm_kernel(const float* __restrict__ bias)
{
    extern __shared__ __half smh[];
    const unsigned sbase = smem_u32(smh);

    const int p0  = blockIdx.x * 128;
    const int b   = blockIdx.y;
    const int tid = threadIdx.x;
    const int wid = tid >> 5;
    const int lane = tid & 31;
    const int wm = wid & 3;
    const int wn = wid >> 2;
    const unsigned lrow = (unsigned)(lane & 15);
    const unsigned lk8  = (unsigned)((lane >> 4) * 8);

    const __half* xT_b = g_xT_h + (size_t)b * HW * C;

    auto issue = [&](int ck) {
        const int k0 = ck * 64;
        const unsigned ws_o = (unsigned)((ck & 1) * TG_WS);
        const unsigned xs_o = (unsigned)(2 * TG_WS + (ck & 1) * TG_XS);
        #pragma unroll
        for (int r = 0; r < 8; ++r) {
            int f = r * 256 + tid;
            int c = f >> 3, ch = f & 7;
            cpa16(sbase + (ws_o + (unsigned)(c * 72 + ch * 8)) * 2,
                  g_W_h + (size_t)c * C + k0 + ch * 8);
        }
        #pragma unroll
        for (int r = 0; r < 4; ++r) {
            int f = r * 256 + tid;
            int p = f >> 3, ch = f & 7;
            cpa16(sbase + (xs_o + (unsigned)(p * 72 + ch * 8)) * 2,
                  xT_b + (size_t)(p0 + p) * C + k0 + ch * 8);
        }
        cpa_commit();
    };

    issue(0);

    float acc[4][8][4];
    #pragma unroll
    for (int m = 0; m < 4; ++m)
        #pragma unroll
        for (int t = 0; t < 8; ++t)
            #pragma unroll
            for (int r = 0; r < 4; ++r) acc[m][t][r] = 0.f;

    for (int ck = 0; ck < 4; ++ck) {
        if (ck + 1 < 4) {
            issue(ck + 1);
            asm volatile("cp.async.wait_group 1;" ::: "memory");
        } else {
            asm volatile("cp.async.wait_group 0;" ::: "memory");
        }
        __syncthreads();
        const unsigned ws_o = (unsigned)((ck & 1) * TG_WS);
        const unsigned xs_o = (unsigned)(2 * TG_WS + (ck & 1) * TG_XS);

        const unsigned aA = sbase + (ws_o + (unsigned)((wm * 64 + lrow) * 72) + lk8) * 2;
        const unsigned aB = sbase + (xs_o + (unsigned)((wn * 64 + lrow) * 72) + lk8) * 2;
        #pragma unroll
        for (int kk = 0; kk < 4; ++kk) {
            unsigned a[4][4], bb[4][4];
            #pragma unroll
            for (int m = 0; m < 4; ++m)
                ldsm_x4(a[m], aA + (unsigned)(m * 16 * 72 * 2) + kk * 32);
            #pragma unroll
            for (int n = 0; n < 4; ++n)
                ldsm_x4(bb[n], aB + (unsigned)(n * 16 * 72 * 2) + kk * 32);
            #pragma unroll
            for (int m = 0; m < 4; ++m)
                #pragma unroll
                for (int n = 0; n < 4; ++n) {
                    mma_f16(acc[m][n * 2 + 0], a[m], bb[n][0], bb[n][2]);
                    mma_f16(acc[m][n * 2 + 1], a[m], bb[n][1], bb[n][3]);
                }
        }
        __syncthreads();
    }

    __half* tb = g_t_h + (size_t)b * C * HW;
    #pragma unroll
    for (int m = 0; m < 4; ++m) {
        const int c0 = wm * 64 + m * 16 + (lane >> 2);
        const float bo0 = __ldg(bias + c0);
        const float bo1 = __ldg(bias + c0 + 8);
        #pragma unroll
        for (int t = 0; t < 8; ++t) {
            const int p = p0 + wn * 64 + t * 8 + (lane & 3) * 2;
            *reinterpret_cast<unsigned*>(tb + (size_t)c0 * HW + p) =
                pack_h2(acc[m][t][0] + bo0, acc[m][t][1] + bo0);
            *reinterpret_cast<unsigned*>(tb + (size_t)(c0 + 8) * HW + p) =
                pack_h2(acc[m][t][2] + bo1, acc[m][t][3] + bo1);
        }
    }
}

// ---------------------------------------------------------------------------
// qbuild: per (pair, b): S = Xn_i Xn_j^T (128x128, K=256), Q = S^2 -> g_Q[i][j]
// Only block-pairs with ti >= tj.
// smem halves: xi 128x264, xj 128x264, qs 128x136
// ---------------------------------------------------------------------------
#define QXI_OFF 0
#define QXJ_OFF 33792
#define QQS_OFF 67584
#define Q_SMEM_H 84992

__global__ void __launch_bounds__(256, 1)
qbuild_kernel()
{
    extern __shared__ __half smh[];
    const unsigned sbase = smem_u32(smh);

    const int p   = blockIdx.x;
    const int b   = blockIdx.y;
    const int tid = threadIdx.x;
    const int wid = tid >> 5;
    const int lane = tid & 31;

    int ti = 0;
    while ((ti + 1) * (ti + 2) / 2 <= p) ++ti;
    const int tj = p - ti * (ti + 1) / 2;
    const int i0 = ti * TI;
    const int j0 = tj * TI;

    const __half* xnT_b = g_xnT_h + (size_t)b * HW * C;

    // Load xi, xj: 128 rows x 32 chunks(16B) each
    #pragma unroll
    for (int r = 0; r < 16; ++r) {
        int f = r * 256 + tid;
        int row = f >> 5, ch = f & 31;
        cpa16(sbase + (unsigned)((QXI_OFF + row * 264 + ch * 8) * 2),
              xnT_b + (size_t)(i0 + row) * C + ch * 8);
        cpa16(sbase + (unsigned)((QXJ_OFF + row * 264 + ch * 8) * 2),
              xnT_b + (size_t)(j0 + row) * C + ch * 8);
    }
    cpa_commit();
    asm volatile("cp.async.wait_group 0;" ::: "memory");
    __syncthreads();

    const int wm = wid & 3;    // i-strip (32 rows)
    const int wn = wid >> 2;   // j-half (64 cols)
    const unsigned lrow = (unsigned)(lane & 15);
    const unsigned lk8  = (unsigned)((lane >> 4) * 8);

    float d[2][8][4];
    #pragma unroll
    for (int m = 0; m < 2; ++m)
        #pragma unroll
        for (int t = 0; t < 8; ++t)
            #pragma unroll
            for (int r = 0; r < 4; ++r) d[m][t][r] = 0.f;

    const unsigned aA = sbase + (unsigned)((QXI_OFF + (wm * 32 + lrow) * 264) + lk8) * 2;
    unsigned aB[4];
    #pragma unroll
    for (int tt = 0; tt < 4; ++tt)
        aB[tt] = sbase + (unsigned)((QXJ_OFF + (wn * 64 + tt * 16 + lrow) * 264) + lk8) * 2;

    #pragma unroll 4
    for (int kk = 0; kk < 16; ++kk) {
        unsigned a[2][4];
        ldsm_x4(a[0], aA + kk * 32);
        ldsm_x4(a[1], aA + 16 * 264 * 2 + kk * 32);
        #pragma unroll
        for (int tt = 0; tt < 4; ++tt) {
            unsigned bb[4];
            ldsm_x4(bb, aB[tt] + kk * 32);
            #pragma unroll
            for (int m = 0; m < 2; ++m) {
                mma_f16(d[m][tt * 2 + 0], a[m], bb[0], bb[2]);
                mma_f16(d[m][tt * 2 + 1], a[m], bb[1], bb[3]);
            }
        }
    }

    // square -> qs (stride 136)
    {
        __half* qsm = smh + QQS_OFF;
        #pragma unroll
        for (int m = 0; m < 2; ++m) {
            const int r0 = wm * 32 + m * 16 + (lane >> 2);
            #pragma unroll
            for (int t = 0; t < 8; ++t) {
                const int col = wn * 64 + t * 8 + (lane & 3) * 2;
                *reinterpret_cast<unsigned*>(qsm + r0 * 136 + col) =
                    pack_h2(d[m][t][0] * d[m][t][0], d[m][t][1] * d[m][t][1]);
                *reinterpret_cast<unsigned*>(qsm + (r0 + 8) * 136 + col) =
                    pack_h2(d[m][t][2] * d[m][t][2], d[m][t][3] * d[m][t][3]);
            }
        }
    }
    __syncthreads();

    // Write tile Q[i0+r][j0+c], rows coalesced (uint2 = 4 halves per lane)
    __half* Qb = g_Q + ((size_t)b * HW * HW);
    #pragma unroll
    for (int rr = 0; rr < 16; ++rr) {
        const int r = wid * 16 + rr;
        uint2 v = *reinterpret_cast<const uint2*>(smh + QQS_OFF + r * 136 + lane * 4);
        *reinterpret_cast<uint2*>(Qb + (size_t)(i0 + r) * HW + j0 + lane * 4) = v;
    }
}

// ---------------------------------------------------------------------------
// propagate: out[b][c][j] = sum_k t[c][k] * Q_sym[k][j]
// CTA: 128 c x 128 j, K=4096 in 64-chunks, double-buffered; 2 CTAs/SM.
// Q_sym[k][j] = Q[k][j] if kblk >= jblk (ldsm.trans, k-major),
//               Q[j][k] if kblk <  jblk (ldsm, n-major).
// smem halves: A 2x(128x72), B 2x(9216)
// ---------------------------------------------------------------------------
#define P_A0 0
#define P_AB 9216
#define P_B0 18432
#define P_BB 9216
#define P_SMEM_H 36864

__global__ void __launch_bounds__(256, 2)
prop_kernel(float* __restrict__ out)
{
    extern __shared__ __half smh[];
    const unsigned sbase = smem_u32(smh);

    const int cs  = blockIdx.x & 1;          // c-strip (128)
    const int jt  = blockIdx.x >> 1;         // j-tile (128)
    const int b   = blockIdx.y;
    const int j0  = jt * TI;
    const int tid = threadIdx.x;
    const int wid = tid >> 5;
    const int lane = tid & 31;

    const int wc = wid & 1;    // c-half (64)
    const int wj = wid >> 1;   // j-quarter (32)
    const unsigned lrow = (unsigned)(lane & 15);
    const unsigned lk8  = (unsigned)((lane >> 4) * 8);
    const unsigned qrow = (unsigned)((((lane >> 3) & 1) * 8) + (lane & 7));

    const __half* t_b = g_t_h + (size_t)b * C * HW;
    const __half* Qb  = g_Q + ((size_t)b * HW * HW);

    auto issue = [&](int ck) {
        const int k0 = ck * 64;
        const int kb = k0 >> 7;
        const unsigned a_o = (unsigned)(P_A0 + (ck & 1) * P_AB);
        const unsigned b_o = (unsigned)(P_B0 + (ck & 1) * P_BB);
        // A: t rows c (128) x 64 k
        #pragma unroll
        for (int r = 0; r < 4; ++r) {
            int f = r * 256 + tid;
            int row = f >> 3, ch = f & 7;
            cpa16(sbase + (a_o + (unsigned)(row * 72 + ch * 8)) * 2,
                  t_b + (size_t)(cs * 128 + row) * HW + k0 + ch * 8);
        }
        if (kb >= jt) {
            // k-major tile: 64 rows(k) x 128 cols(j), stride 136
            #pragma unroll
            for (int r = 0; r < 4; ++r) {
                int f = r * 256 + tid;
                int row = f >> 4, ch = f & 15;
                cpa16(sbase + (b_o + (unsigned)(row * 136 + ch * 8)) * 2,
                      Qb + (size_t)(k0 + row) * HW + j0 + ch * 8);
            }
        } else {
            // j-major tile: 128 rows(j) x 64 cols(k), stride 72
            #pragma unroll
            for (int r = 0; r < 4; ++r) {
                int f = r * 256 + tid;
                int row = f >> 3, ch = f & 7;
                cpa16(sbase + (b_o + (unsigned)(row * 72 + ch * 8)) * 2,
                      Qb + (size_t)(j0 + row) * HW + k0 + ch * 8);
            }
        }
        cpa_commit();
    };

    issue(0);

    float acc[4][4][4];
    #pragma unroll
    for (int s = 0; s < 4; ++s)
        #pragma unroll
        for (int t = 0; t < 4; ++t)
            #pragma unroll
            for (int r = 0; r < 4; ++r) acc[s][t][r] = 0.f;

    for (int ck = 0; ck < HW / 64; ++ck) {
        if (ck + 1 < HW / 64) {
            issue(ck + 1);
            asm volatile("cp.async.wait_group 1;" ::: "memory");
        } else {
            asm volatile("cp.async.wait_group 0;" ::: "memory");
        }
        __syncthreads();

        const int k0 = ck * 64;
        const int kb = k0 >> 7;
        const unsigned a_o = (unsigned)(P_A0 + (ck & 1) * P_AB);
        const unsigned b_o = (unsigned)(P_B0 + (ck & 1) * P_BB);
        const unsigned aA = sbase + (a_o + (unsigned)((wc * 64 + lrow) * 72) + lk8) * 2;

        if (kb >= jt) {
            #pragma unroll
            for (int kk = 0; kk < 4; ++kk) {
                unsigned aa[4][4];
                #pragma unroll
                for (int s = 0; s < 4; ++s)
                    ldsm_x4(aa[s], aA + (unsigned)(s * 16 * 72 * 2) + kk * 32);
                #pragma unroll
                for (int tp = 0; tp < 2; ++tp) {
                    unsigned bq[4];
                    ldsm_x4t(bq, sbase + (b_o + (unsigned)((kk * 16 + qrow) * 136 +
                                                           wj * 32 + tp * 16) + lk8) * 2);
                    #pragma unroll
                    for (int s = 0; s < 4; ++s) {
                        mma_f16(acc[s][tp * 2 + 0], aa[s], bq[0], bq[1]);
                        mma_f16(acc[s][tp * 2 + 1], aa[s], bq[2], bq[3]);
                    }
                }
            }
        } else {
            #pragma unroll
            for (int kk = 0; kk < 4; ++kk) {
                unsigned aa[4][4];
                #pragma unroll
                for (int s = 0; s < 4; ++s)
                    ldsm_x4(aa[s], aA + (unsigned)(s * 16 * 72 * 2) + kk * 32);
                #pragma unroll
                for (int tt = 0; tt < 2; ++tt) {
                    unsigned bb[4];
                    ldsm_x4(bb, sbase + (b_o + (unsigned)((wj * 32 + tt * 16 + lrow) * 72) +
                                         (unsigned)(kk * 16) + lk8) * 2);
                    #pragma unroll
                    for (int s = 0; s < 4; ++s) {
                        mma_f16(acc[s][tt * 2 + 0], aa[s], bb[0], bb[2]);
                        mma_f16(acc[s][tt * 2 + 1], aa[s], bb[1], bb[3]);
                    }
                }
            }
        }
        __syncthreads();
    }

    // Write out[b][c][j]
    float* ob = out + (size_t)b * C * HW;
    #pragma unroll
    for (int s = 0; s < 4; ++s) {
        const int c0 = cs * 128 + wc * 64 + s * 16 + (lane >> 2);
        #pragma unroll
        for (int t = 0; t < 4; ++t) {
            const int col = j0 + wj * 32 + t * 8 + (lane & 3) * 2;
            *reinterpret_cast<float2*>(ob + (size_t)c0 * HW + col) =
                make_float2(acc[s][t][0], acc[s][t][1]);
            *reinterpret_cast<float2*>(ob + (size_t)(c0 + 8) * HW + col) =
                make_float2(acc[s][t][2], acc[s][t][3]);
        }
    }
}

// ---------------------------------------------------------------------------
extern "C" void kernel_launch(void* const* d_in, const int* in_sizes, int n_in,
                              void* d_out, int out_size)
{
    const float* x    = (const float*)d_in[0];
    const float* W    = (const float*)d_in[1];
    const float* bias = (const float*)d_in[2];
    float* out        = (float*)d_out;

    const int PREP_SMEM = (C * 68 + 64) * 4;
    const int TG_SMEM   = TG_SMEM_H * 2;
    const int Q_SMEM    = Q_SMEM_H * 2;      // 169,984 B
    const int P_SMEM    = P_SMEM_H * 2;      // 73,728 B -> 2 CTAs/SM

    cudaFuncSetAttribute(prep_kernel,   cudaFuncAttributeMaxDynamicSharedMemorySize, PREP_SMEM);
    cudaFuncSetAttribute(tgemm_kernel,  cudaFuncAttributeMaxDynamicSharedMemorySize, TG_SMEM);
    cudaFuncSetAttribute(qbuild_kernel, cudaFuncAttributeMaxDynamicSharedMemorySize, Q_SMEM);
    cudaFuncSetAttribute(prop_kernel,   cudaFuncAttributeMaxDynamicSharedMemorySize, P_SMEM);

    conv_w_kernel<<<64, 256>>>(W);

    dim3 g1(HW / PT, BATCH);
    prep_kernel<<<g1, 256, PREP_SMEM>>>(x);

    dim3 gt(HW / 128, BATCH);
    tgemm_kernel<<<gt, 256, TG_SMEM>>>(bias);

    dim3 gq(NPAIR, BATCH);
    qbuild_kernel<<<gq, 256, Q_SMEM>>>();

    dim3 gp(2 * NTI, BATCH);
    prop_kernel<<<gp, 256, P_SMEM>>>(out);
}

// round 9
// speedup vs baseline: 10.3423x; 1.0953x over previous
#include <cuda_runtime.h>
#include <cuda_fp16.h>

#define BATCH 8
#define C 256
#define HW 4096
#define PT 64
#define TI 128
#define NTI (HW / TI)              // 32
#define NPAIR (NTI * (NTI + 1) / 2)  // 528

// Global scratch (fp16)
__device__ __half g_xnT_h[(size_t)BATCH * HW * C];  // normalized, pixel-major (p, c)
__device__ __half g_xT_h [(size_t)BATCH * HW * C];  // raw,        pixel-major (p, c)
__device__ __half g_t_h  [(size_t)BATCH * C * HW];  // t = Wx+b,   c-major (c, p)
__device__ __half g_W_h  [C * C];                   // W fp16
__device__ __half g_Q    [(size_t)BATCH * HW * HW]; // Q = S^2, lower-block-triangle only

__device__ __forceinline__ unsigned smem_u32(const void* p) {
    unsigned a;
    asm("{ .reg .u64 t; cvta.to.shared.u64 t, %1; cvt.u32.u64 %0, t; }" : "=r"(a) : "l"(p));
    return a;
}
__device__ __forceinline__ void cpa16(unsigned dst, const void* src) {
    asm volatile("cp.async.cg.shared.global [%0], [%1], 16;" :: "r"(dst), "l"(src) : "memory");
}
__device__ __forceinline__ void cpa_commit() {
    asm volatile("cp.async.commit_group;" ::: "memory");
}
__device__ __forceinline__ void ldsm_x4(unsigned* r, unsigned addr) {
    asm volatile("ldmatrix.sync.aligned.m8n8.x4.shared.b16 {%0,%1,%2,%3}, [%4];"
                 : "=r"(r[0]), "=r"(r[1]), "=r"(r[2]), "=r"(r[3]) : "r"(addr));
}
__device__ __forceinline__ void ldsm_x4t(unsigned* r, unsigned addr) {
    asm volatile("ldmatrix.sync.aligned.m8n8.x4.trans.shared.b16 {%0,%1,%2,%3}, [%4];"
                 : "=r"(r[0]), "=r"(r[1]), "=r"(r[2]), "=r"(r[3]) : "r"(addr));
}
__device__ __forceinline__ void mma_f16(float d[4], const unsigned a[4], unsigned b0, unsigned b1) {
    asm volatile(
        "mma.sync.aligned.m16n8k16.row.col.f32.f16.f16.f32 "
        "{%0,%1,%2,%3}, {%4,%5,%6,%7}, {%8,%9}, {%0,%1,%2,%3};"
        : "+f"(d[0]), "+f"(d[1]), "+f"(d[2]), "+f"(d[3])
        : "r"(a[0]), "r"(a[1]), "r"(a[2]), "r"(a[3]), "r"(b0), "r"(b1));
}
__device__ __forceinline__ unsigned pack_h2(float a, float b) {
    __half2 h = __floats2half2_rn(a, b);
    return *reinterpret_cast<unsigned*>(&h);
}

// ---------------------------------------------------------------------------
__global__ void conv_w_kernel(const float* __restrict__ W) {
    int i = (blockIdx.x * 256 + threadIdx.x) * 4;
    float4 v = *reinterpret_cast<const float4*>(W + i);
    uint2 u;
    u.x = pack_h2(v.x, v.y);
    u.y = pack_h2(v.z, v.w);
    *reinterpret_cast<uint2*>(g_W_h + i) = u;
}

// ---------------------------------------------------------------------------
// Prep: per (b, 64-pixel tile): invn, write xnT_h (normalized) + xT_h (raw)
// ---------------------------------------------------------------------------
__global__ void __launch_bounds__(256, 1)
prep_kernel(const float* __restrict__ x)
{
    extern __shared__ float sm[];
    float* xs   = sm;                  // C * 68
    float* invn = xs + C * 68;         // 64

    const int p0  = blockIdx.x * PT;
    const int b   = blockIdx.y;
    const int tid = threadIdx.x;
    const float* xb = x + (size_t)b * C * HW;

    #pragma unroll
    for (int r = 0; r < 16; ++r) {
        int f4 = r * 256 + tid;
        int c  = f4 >> 4;
        int kq = f4 & 15;
        float4 v = *reinterpret_cast<const float4*>(xb + (size_t)c * HW + p0 + kq * 4);
        *reinterpret_cast<float4*>(xs + c * 68 + kq * 4) = v;
    }
    __syncthreads();

    if (tid < 64) {
        float s = 0.f;
        #pragma unroll 8
        for (int c = 0; c < C; ++c) { float v = xs[c * 68 + tid]; s += v * v; }
        invn[tid] = 1.0f / fmaxf(sqrtf(s), 1e-12f);
    }
    __syncthreads();

    {
        int p   = tid & 63;
        int grp = tid >> 6;
        float inv = invn[p];
        __half* dn = g_xnT_h + ((size_t)b * HW + p0 + p) * C;
        __half* dr = g_xT_h  + ((size_t)b * HW + p0 + p) * C;
        #pragma unroll
        for (int cc = 0; cc < 16; ++cc) {
            int c = grp * 64 + cc * 4;
            float v0 = xs[(c + 0) * 68 + p], v1 = xs[(c + 1) * 68 + p];
            float v2 = xs[(c + 2) * 68 + p], v3 = xs[(c + 3) * 68 + p];
            uint2 un, ur;
            un.x = pack_h2(v0 * inv, v1 * inv);
            un.y = pack_h2(v2 * inv, v3 * inv);
            ur.x = pack_h2(v0, v1);
            ur.y = pack_h2(v2, v3);
            *reinterpret_cast<uint2*>(dn + c) = un;
            *reinterpret_cast<uint2*>(dr + c) = ur;
        }
    }
}

// ---------------------------------------------------------------------------
// tgemm: t[c][p] = sum_k W[c][k] x[k][p] + bias[c]
// ---------------------------------------------------------------------------
#define TG_WS 18432
#define TG_XS 9216
#define TG_SMEM_H (2 * TG_WS + 2 * TG_XS)

__global__ void __launch_bounds__(256, 1)
tgemm_kernel(const float* __restrict__ bias)
{
    extern __shared__ __half smh[];
    const unsigned sbase = smem_u32(smh);

    const int p0  = blockIdx.x * 128;
    const int b   = blockIdx.y;
    const int tid = threadIdx.x;
    const int wid = tid >> 5;
    const int lane = tid & 31;
    const int wm = wid & 3;
    const int wn = wid >> 2;
    const unsigned lrow = (unsigned)(lane & 15);
    const unsigned lk8  = (unsigned)((lane >> 4) * 8);

    const __half* xT_b = g_xT_h + (size_t)b * HW * C;

    auto issue = [&](int ck) {
        const int k0 = ck * 64;
        const unsigned ws_o = (unsigned)((ck & 1) * TG_WS);
        const unsigned xs_o = (unsigned)(2 * TG_WS + (ck & 1) * TG_XS);
        #pragma unroll
        for (int r = 0; r < 8; ++r) {
            int f = r * 256 + tid;
            int c = f >> 3, ch = f & 7;
            cpa16(sbase + (ws_o + (unsigned)(c * 72 + ch * 8)) * 2,
                  g_W_h + (size_t)c * C + k0 + ch * 8);
        }
        #pragma unroll
        for (int r = 0; r < 4; ++r) {
            int f = r * 256 + tid;
            int p = f >> 3, ch = f & 7;
            cpa16(sbase + (xs_o + (unsigned)(p * 72 + ch * 8)) * 2,
                  xT_b + (size_t)(p0 + p) * C + k0 + ch * 8);
        }
        cpa_commit();
    };

    issue(0);

    float acc[4][8][4];
    #pragma unroll
    for (int m = 0; m < 4; ++m)
        #pragma unroll
        for (int t = 0; t < 8; ++t)
            #pragma unroll
            for (int r = 0; r < 4; ++r) acc[m][t][r] = 0.f;

    for (int ck = 0; ck < 4; ++ck) {
        if (ck + 1 < 4) {
            issue(ck + 1);
            asm volatile("cp.async.wait_group 1;" ::: "memory");
        } else {
            asm volatile("cp.async.wait_group 0;" ::: "memory");
        }
        __syncthreads();
        const unsigned ws_o = (unsigned)((ck & 1) * TG_WS);
        const unsigned xs_o = (unsigned)(2 * TG_WS + (ck & 1) * TG_XS);

        const unsigned aA = sbase + (ws_o + (unsigned)((wm * 64 + lrow) * 72) + lk8) * 2;
        const unsigned aB = sbase + (xs_o + (unsigned)((wn * 64 + lrow) * 72) + lk8) * 2;
        #pragma unroll
        for (int kk = 0; kk < 4; ++kk) {
            unsigned a[4][4], bb[4][4];
            #pragma unroll
            for (int m = 0; m < 4; ++m)
                ldsm_x4(a[m], aA + (unsigned)(m * 16 * 72 * 2) + kk * 32);
            #pragma unroll
            for (int n = 0; n < 4; ++n)
                ldsm_x4(bb[n], aB + (unsigned)(n * 16 * 72 * 2) + kk * 32);
            #pragma unroll
            for (int m = 0; m < 4; ++m)
                #pragma unroll
                for (int n = 0; n < 4; ++n) {
                    mma_f16(acc[m][n * 2 + 0], a[m], bb[n][0], bb[n][2]);
                    mma_f16(acc[m][n * 2 + 1], a[m], bb[n][1], bb[n][3]);
                }
        }
        __syncthreads();
    }

    __half* tb = g_t_h + (size_t)b * C * HW;
    #pragma unroll
    for (int m = 0; m < 4; ++m) {
        const int c0 = wm * 64 + m * 16 + (lane >> 2);
        const float bo0 = __ldg(bias + c0);
        const float bo1 = __ldg(bias + c0 + 8);
        #pragma unroll
        for (int t = 0; t < 8; ++t) {
            const int p = p0 + wn * 64 + t * 8 + (lane & 3) * 2;
            *reinterpret_cast<unsigned*>(tb + (size_t)c0 * HW + p) =
                pack_h2(acc[m][t][0] + bo0, acc[m][t][1] + bo0);
            *reinterpret_cast<unsigned*>(tb + (size_t)(c0 + 8) * HW + p) =
                pack_h2(acc[m][t][2] + bo1, acc[m][t][3] + bo1);
        }
    }
}

// ---------------------------------------------------------------------------
// qbuild: per (pair, b): S = Xn_i Xn_j^T (128x128, K=256 in two 128-chunks),
//         Q = S^2 -> g_Q[i][j].  Only block-pairs with ti >= tj.
// smem halves: xi 128x136, xj 128x136, qs 128x136 = 104,448 B -> 2 CTAs/SM
// ---------------------------------------------------------------------------
#define QX_ST   136
#define QXI_OFF 0
#define QXJ_OFF 17408
#define QQS_OFF 34816
#define Q_SMEM_H 52224

__global__ void __launch_bounds__(256, 2)
qbuild_kernel()
{
    extern __shared__ __half smh[];
    const unsigned sbase = smem_u32(smh);

    const int p   = blockIdx.x;
    const int b   = blockIdx.y;
    const int tid = threadIdx.x;
    const int wid = tid >> 5;
    const int lane = tid & 31;

    int ti = 0;
    while ((ti + 1) * (ti + 2) / 2 <= p) ++ti;
    const int tj = p - ti * (ti + 1) / 2;
    const int i0 = ti * TI;
    const int j0 = tj * TI;

    const __half* xnT_b = g_xnT_h + (size_t)b * HW * C;

    const int wm = wid & 3;    // i-strip (32 rows)
    const int wn = wid >> 2;   // j-half (64 cols)
    const unsigned lrow = (unsigned)(lane & 15);
    const unsigned lk8  = (unsigned)((lane >> 4) * 8);

    float d[2][8][4];
    #pragma unroll
    for (int m = 0; m < 2; ++m)
        #pragma unroll
        for (int t = 0; t < 8; ++t)
            #pragma unroll
            for (int r = 0; r < 4; ++r) d[m][t][r] = 0.f;

    const unsigned aA = sbase + (unsigned)((QXI_OFF + (wm * 32 + lrow) * QX_ST) + lk8) * 2;
    unsigned aB[4];
    #pragma unroll
    for (int tt = 0; tt < 4; ++tt)
        aB[tt] = sbase + (unsigned)((QXJ_OFF + (wn * 64 + tt * 16 + lrow) * QX_ST) + lk8) * 2;

    for (int kc = 0; kc < 2; ++kc) {
        const int kb = kc * 128;
        // Load xi/xj chunk: 128 rows x 16 chunks(16B) each
        #pragma unroll
        for (int r = 0; r < 8; ++r) {
            int f = r * 256 + tid;
            int row = f >> 4, ch = f & 15;
            cpa16(sbase + (unsigned)((QXI_OFF + row * QX_ST + ch * 8) * 2),
                  xnT_b + (size_t)(i0 + row) * C + kb + ch * 8);
            cpa16(sbase + (unsigned)((QXJ_OFF + row * QX_ST + ch * 8) * 2),
                  xnT_b + (size_t)(j0 + row) * C + kb + ch * 8);
        }
        cpa_commit();
        asm volatile("cp.async.wait_group 0;" ::: "memory");
        __syncthreads();

        #pragma unroll 4
        for (int kk = 0; kk < 8; ++kk) {
            unsigned a[2][4];
            ldsm_x4(a[0], aA + kk * 32);
            ldsm_x4(a[1], aA + 16 * QX_ST * 2 + kk * 32);
            #pragma unroll
            for (int tt = 0; tt < 4; ++tt) {
                unsigned bb[4];
                ldsm_x4(bb, aB[tt] + kk * 32);
                #pragma unroll
                for (int m = 0; m < 2; ++m) {
                    mma_f16(d[m][tt * 2 + 0], a[m], bb[0], bb[2]);
                    mma_f16(d[m][tt * 2 + 1], a[m], bb[1], bb[3]);
                }
            }
        }
        __syncthreads();   // chunk consumed before reload
    }

    // square -> qs (stride 136)
    {
        __half* qsm = smh + QQS_OFF;
        #pragma unroll
        for (int m = 0; m < 2; ++m) {
            const int r0 = wm * 32 + m * 16 + (lane >> 2);
            #pragma unroll
            for (int t = 0; t < 8; ++t) {
                const int col = wn * 64 + t * 8 + (lane & 3) * 2;
                *reinterpret_cast<unsigned*>(qsm + r0 * QX_ST + col) =
                    pack_h2(d[m][t][0] * d[m][t][0], d[m][t][1] * d[m][t][1]);
                *reinterpret_cast<unsigned*>(qsm + (r0 + 8) * QX_ST + col) =
                    pack_h2(d[m][t][2] * d[m][t][2], d[m][t][3] * d[m][t][3]);
            }
        }
    }
    __syncthreads();

    // Write tile Q[i0+r][j0+c], rows coalesced (uint2 = 4 halves per lane)
    __half* Qb = g_Q + ((size_t)b * HW * HW);
    #pragma unroll
    for (int rr = 0; rr < 16; ++rr) {
        const int r = wid * 16 + rr;
        uint2 v = *reinterpret_cast<const uint2*>(smh + QQS_OFF + r * QX_ST + lane * 4);
        *reinterpret_cast<uint2*>(Qb + (size_t)(i0 + r) * HW + j0 + lane * 4) = v;
    }
}

// ---------------------------------------------------------------------------
// propagate: out[b][c][j] = sum_k t[c][k] * Q_sym[k][j]
// CTA: 128 c x 128 j, K=4096 in 64-chunks, double-buffered; 2 CTAs/SM.
// ---------------------------------------------------------------------------
#define P_A0 0
#define P_AB 9216
#define P_B0 18432
#define P_BB 9216
#define P_SMEM_H 36864

__global__ void __launch_bounds__(256, 2)
prop_kernel(float* __restrict__ out)
{
    extern __shared__ __half smh[];
    const unsigned sbase = smem_u32(smh);

    const int cs  = blockIdx.x & 1;          // c-strip (128)
    const int jt  = blockIdx.x >> 1;         // j-tile (128)
    const int b   = blockIdx.y;
    const int j0  = jt * TI;
    const int tid = threadIdx.x;
    const int wid = tid >> 5;
    const int lane = tid & 31;

    const int wc = wid & 1;    // c-half (64)
    const int wj = wid >> 1;   // j-quarter (32)
    const unsigned lrow = (unsigned)(lane & 15);
    const unsigned lk8  = (unsigned)((lane >> 4) * 8);
    const unsigned qrow = (unsigned)((((lane >> 3) & 1) * 8) + (lane & 7));

    const __half* t_b = g_t_h + (size_t)b * C * HW;
    const __half* Qb  = g_Q + ((size_t)b * HW * HW);

    auto issue = [&](int ck) {
        const int k0 = ck * 64;
        const int kb = k0 >> 7;
        const unsigned a_o = (unsigned)(P_A0 + (ck & 1) * P_AB);
        const unsigned b_o = (unsigned)(P_B0 + (ck & 1) * P_BB);
        #pragma unroll
        for (int r = 0; r < 4; ++r) {
            int f = r * 256 + tid;
            int row = f >> 3, ch = f & 7;
            cpa16(sbase + (a_o + (unsigned)(row * 72 + ch * 8)) * 2,
                  t_b + (size_t)(cs * 128 + row) * HW + k0 + ch * 8);
        }
        if (kb >= jt) {
            #pragma unroll
            for (int r = 0; r < 4; ++r) {
                int f = r * 256 + tid;
                int row = f >> 4, ch = f & 15;
                cpa16(sbase + (b_o + (unsigned)(row * 136 + ch * 8)) * 2,
                      Qb + (size_t)(k0 + row) * HW + j0 + ch * 8);
            }
        } else {
            #pragma unroll
            for (int r = 0; r < 4; ++r) {
                int f = r * 256 + tid;
                int row = f >> 3, ch = f & 7;
                cpa16(sbase + (b_o + (unsigned)(row * 72 + ch * 8)) * 2,
                      Qb + (size_t)(j0 + row) * HW + k0 + ch * 8);
            }
        }
        cpa_commit();
    };

    issue(0);

    float acc[4][4][4];
    #pragma unroll
    for (int s = 0; s < 4; ++s)
        #pragma unroll
        for (int t = 0; t < 4; ++t)
            #pragma unroll
            for (int r = 0; r < 4; ++r) acc[s][t][r] = 0.f;

    for (int ck = 0; ck < HW / 64; ++ck) {
        if (ck + 1 < HW / 64) {
            issue(ck + 1);
            asm volatile("cp.async.wait_group 1;" ::: "memory");
        } else {
            asm volatile("cp.async.wait_group 0;" ::: "memory");
        }
        __syncthreads();

        const int k0 = ck * 64;
        const int kb = k0 >> 7;
        const unsigned a_o = (unsigned)(P_A0 + (ck & 1) * P_AB);
        const unsigned b_o = (unsigned)(P_B0 + (ck & 1) * P_BB);
        const unsigned aA = sbase + (a_o + (unsigned)((wc * 64 + lrow) * 72) + lk8) * 2;

        if (kb >= jt) {
            #pragma unroll
            for (int kk = 0; kk < 4; ++kk) {
                unsigned aa[4][4];
                #pragma unroll
                for (int s = 0; s < 4; ++s)
                    ldsm_x4(aa[s], aA + (unsigned)(s * 16 * 72 * 2) + kk * 32);
                #pragma unroll
                for (int tp = 0; tp < 2; ++tp) {
                    unsigned bq[4];
                    ldsm_x4t(bq, sbase + (b_o + (unsigned)((kk * 16 + qrow) * 136 +
                                                           wj * 32 + tp * 16) + lk8) * 2);
                    #pragma unroll
                    for (int s = 0; s < 4; ++s) {
                        mma_f16(acc[s][tp * 2 + 0], aa[s], bq[0], bq[1]);
                        mma_f16(acc[s][tp * 2 + 1], aa[s], bq[2], bq[3]);
                    }
                }
            }
        } else {
            #pragma unroll
            for (int kk = 0; kk < 4; ++kk) {
                unsigned aa[4][4];
                #pragma unroll
                for (int s = 0; s < 4; ++s)
                    ldsm_x4(aa[s], aA + (unsigned)(s * 16 * 72 * 2) + kk * 32);
                #pragma unroll
                for (int tt = 0; tt < 2; ++tt) {
                    unsigned bb[4];
                    ldsm_x4(bb, sbase + (b_o + (unsigned)((wj * 32 + tt * 16 + lrow) * 72) +
                                         (unsigned)(kk * 16) + lk8) * 2);
                    #pragma unroll
                    for (int s = 0; s < 4; ++s) {
                        mma_f16(acc[s][tt * 2 + 0], aa[s], bb[0], bb[2]);
                        mma_f16(acc[s][tt * 2 + 1], aa[s], bb[1], bb[3]);
                    }
                }
            }
        }
        __syncthreads();
    }

    float* ob = out + (size_t)b * C * HW;
    #pragma unroll
    for (int s = 0; s < 4; ++s) {
        const int c0 = cs * 128 + wc * 64 + s * 16 + (lane >> 2);
        #pragma unroll
        for (int t = 0; t < 4; ++t) {
            const int col = j0 + wj * 32 + t * 8 + (lane & 3) * 2;
            *reinterpret_cast<float2*>(ob + (size_t)c0 * HW + col) =
                make_float2(acc[s][t][0], acc[s][t][1]);
            *reinterpret_cast<float2*>(ob + (size_t)(c0 + 8) * HW + col) =
                make_float2(acc[s][t][2], acc[s][t][3]);
        }
    }
}

// ---------------------------------------------------------------------------
extern "C" void kernel_launch(void* const* d_in, const int* in_sizes, int n_in,
                              void* d_out, int out_size)
{
    const float* x    = (const float*)d_in[0];
    const float* W    = (const float*)d_in[1];
    const float* bias = (const float*)d_in[2];
    float* out        = (float*)d_out;

    const int PREP_SMEM = (C * 68 + 64) * 4;
    const int TG_SMEM   = TG_SMEM_H * 2;
    const int Q_SMEM    = Q_SMEM_H * 2;      // 104,448 B -> 2 CTAs/SM
    const int P_SMEM    = P_SMEM_H * 2;      // 73,728 B  -> 2 CTAs/SM

    cudaFuncSetAttribute(prep_kernel,   cudaFuncAttributeMaxDynamicSharedMemorySize, PREP_SMEM);
    cudaFuncSetAttribute(tgemm_kernel,  cudaFuncAttributeMaxDynamicSharedMemorySize, TG_SMEM);
    cudaFuncSetAttribute(qbuild_kernel, cudaFuncAttributeMaxDynamicSharedMemorySize, Q_SMEM);
    cudaFuncSetAttribute(prop_kernel,   cudaFuncAttributeMaxDynamicSharedMemorySize, P_SMEM);

    conv_w_kernel<<<64, 256>>>(W);

    dim3 g1(HW / PT, BATCH);
    prep_kernel<<<g1, 256, PREP_SMEM>>>(x);

    dim3 gt(HW / 128, BATCH);
    tgemm_kernel<<<gt, 256, TG_SMEM>>>(bias);

    dim3 gq(NPAIR, BATCH);
    qbuild_kernel<<<gq, 256, Q_SMEM>>>();

    dim3 gp(2 * NTI, BATCH);
    prop_kernel<<<gp, 256, P_SMEM>>>(out);
}

// round 10
// speedup vs baseline: 10.5768x; 1.0227x over previous
#include <cuda_runtime.h>
#include <cuda_fp16.h>

#define BATCH 8
#define C 256
#define HW 4096
#define PT 64
#define TI 128
#define NTI (HW / TI)                // 32
#define NPAIR (NTI * (NTI + 1) / 2)  // 528

// Global scratch
__device__ __half g_xnT_h[(size_t)BATCH * HW * C];  // normalized, pixel-major (p, c)
__device__ float  g_norm [(size_t)BATCH * HW];      // channel L2 norm per pixel
__device__ __half g_t_h  [(size_t)BATCH * C * HW];  // t = Wx+b, c-major (c, p)
__device__ __half g_W_h  [C * C];                   // W fp16
__device__ __half g_Q    [(size_t)BATCH * HW * HW]; // Q = S^2, lower-block-triangle only

__device__ __forceinline__ unsigned smem_u32(const void* p) {
    unsigned a;
    asm("{ .reg .u64 t; cvta.to.shared.u64 t, %1; cvt.u32.u64 %0, t; }" : "=r"(a) : "l"(p));
    return a;
}
__device__ __forceinline__ void cpa16(unsigned dst, const void* src) {
    asm volatile("cp.async.cg.shared.global [%0], [%1], 16;" :: "r"(dst), "l"(src) : "memory");
}
__device__ __forceinline__ void cpa_commit() {
    asm volatile("cp.async.commit_group;" ::: "memory");
}
__device__ __forceinline__ void ldsm_x4(unsigned* r, unsigned addr) {
    asm volatile("ldmatrix.sync.aligned.m8n8.x4.shared.b16 {%0,%1,%2,%3}, [%4];"
                 : "=r"(r[0]), "=r"(r[1]), "=r"(r[2]), "=r"(r[3]) : "r"(addr));
}
__device__ __forceinline__ void ldsm_x4t(unsigned* r, unsigned addr) {
    asm volatile("ldmatrix.sync.aligned.m8n8.x4.trans.shared.b16 {%0,%1,%2,%3}, [%4];"
                 : "=r"(r[0]), "=r"(r[1]), "=r"(r[2]), "=r"(r[3]) : "r"(addr));
}
__device__ __forceinline__ void mma_f16(float d[4], const unsigned a[4], unsigned b0, unsigned b1) {
    asm volatile(
        "mma.sync.aligned.m16n8k16.row.col.f32.f16.f16.f32 "
        "{%0,%1,%2,%3}, {%4,%5,%6,%7}, {%8,%9}, {%0,%1,%2,%3};"
        : "+f"(d[0]), "+f"(d[1]), "+f"(d[2]), "+f"(d[3])
        : "r"(a[0]), "r"(a[1]), "r"(a[2]), "r"(a[3]), "r"(b0), "r"(b1));
}
__device__ __forceinline__ unsigned pack_h2(float a, float b) {
    __half2 h = __floats2half2_rn(a, b);
    return *reinterpret_cast<unsigned*>(&h);
}

// ---------------------------------------------------------------------------
__global__ void conv_w_kernel(const float* __restrict__ W) {
    int i = (blockIdx.x * 256 + threadIdx.x) * 4;
    float4 v = *reinterpret_cast<const float4*>(W + i);
    uint2 u;
    u.x = pack_h2(v.x, v.y);
    u.y = pack_h2(v.z, v.w);
    *reinterpret_cast<uint2*>(g_W_h + i) = u;
}

// ---------------------------------------------------------------------------
// Prep: invn + write xnT_h (normalized, fp16) + g_norm (fp32)
// ---------------------------------------------------------------------------
__global__ void __launch_bounds__(256, 1)
prep_kernel(const float* __restrict__ x)
{
    extern __shared__ float sm[];
    float* xs   = sm;                  // C * 68
    float* invn = xs + C * 68;         // 64

    const int p0  = blockIdx.x * PT;
    const int b   = blockIdx.y;
    const int tid = threadIdx.x;
    const float* xb = x + (size_t)b * C * HW;

    #pragma unroll
    for (int r = 0; r < 16; ++r) {
        int f4 = r * 256 + tid;
        int c  = f4 >> 4;
        int kq = f4 & 15;
        float4 v = *reinterpret_cast<const float4*>(xb + (size_t)c * HW + p0 + kq * 4);
        *reinterpret_cast<float4*>(xs + c * 68 + kq * 4) = v;
    }
    __syncthreads();

    if (tid < 64) {
        float s = 0.f;
        #pragma unroll 8
        for (int c = 0; c < C; ++c) { float v = xs[c * 68 + tid]; s += v * v; }
        float nrm = fmaxf(sqrtf(s), 1e-12f);
        g_norm[(size_t)b * HW + p0 + tid] = nrm;
        invn[tid] = 1.0f / nrm;
    }
    __syncthreads();

    {
        int p   = tid & 63;
        int grp = tid >> 6;
        float inv = invn[p];
        __half* dn = g_xnT_h + ((size_t)b * HW + p0 + p) * C;
        #pragma unroll
        for (int cc = 0; cc < 16; ++cc) {
            int c = grp * 64 + cc * 4;
            uint2 un;
            un.x = pack_h2(xs[(c + 0) * 68 + p] * inv, xs[(c + 1) * 68 + p] * inv);
            un.y = pack_h2(xs[(c + 2) * 68 + p] * inv, xs[(c + 3) * 68 + p] * inv);
            *reinterpret_cast<uint2*>(dn + c) = un;
        }
    }
}

// ---------------------------------------------------------------------------
// tgemm: t[c][p] = norm[p] * (W @ xn)[c][p] + bias[c]
// ---------------------------------------------------------------------------
#define TG_WS 18432
#define TG_XS 9216
#define TG_SMEM_H (2 * TG_WS + 2 * TG_XS)

__global__ void __launch_bounds__(256, 1)
tgemm_kernel(const float* __restrict__ bias)
{
    extern __shared__ __half smh[];
    const unsigned sbase = smem_u32(smh);

    const int p0  = blockIdx.x * 128;
    const int b   = blockIdx.y;
    const int tid = threadIdx.x;
    const int wid = tid >> 5;
    const int lane = tid & 31;
    const int wm = wid & 3;
    const int wn = wid >> 2;
    const unsigned lrow = (unsigned)(lane & 15);
    const unsigned lk8  = (unsigned)((lane >> 4) * 8);

    const __half* xn_b = g_xnT_h + (size_t)b * HW * C;

    auto issue = [&](int ck) {
        const int k0 = ck * 64;
        const unsigned ws_o = (unsigned)((ck & 1) * TG_WS);
        const unsigned xs_o = (unsigned)(2 * TG_WS + (ck & 1) * TG_XS);
        #pragma unroll
        for (int r = 0; r < 8; ++r) {
            int f = r * 256 + tid;
            int c = f >> 3, ch = f & 7;
            cpa16(sbase + (ws_o + (unsigned)(c * 72 + ch * 8)) * 2,
                  g_W_h + (size_t)c * C + k0 + ch * 8);
        }
        #pragma unroll
        for (int r = 0; r < 4; ++r) {
            int f = r * 256 + tid;
            int p = f >> 3, ch = f & 7;
            cpa16(sbase + (xs_o + (unsigned)(p * 72 + ch * 8)) * 2,
                  xn_b + (size_t)(p0 + p) * C + k0 + ch * 8);
        }
        cpa_commit();
    };

    issue(0);

    float acc[4][8][4];
    #pragma unroll
    for (int m = 0; m < 4; ++m)
        #pragma unroll
        for (int t = 0; t < 8; ++t)
            #pragma unroll
            for (int r = 0; r < 4; ++r) acc[m][t][r] = 0.f;

    for (int ck = 0; ck < 4; ++ck) {
        if (ck + 1 < 4) {
            issue(ck + 1);
            asm volatile("cp.async.wait_group 1;" ::: "memory");
        } else {
            asm volatile("cp.async.wait_group 0;" ::: "memory");
        }
        __syncthreads();
        const unsigned ws_o = (unsigned)((ck & 1) * TG_WS);
        const unsigned xs_o = (unsigned)(2 * TG_WS + (ck & 1) * TG_XS);

        const unsigned aA = sbase + (ws_o + (unsigned)((wm * 64 + lrow) * 72) + lk8) * 2;
        const unsigned aB = sbase + (xs_o + (unsigned)((wn * 64 + lrow) * 72) + lk8) * 2;
        #pragma unroll
        for (int kk = 0; kk < 4; ++kk) {
            unsigned a[4][4], bb[4][4];
            #pragma unroll
            for (int m = 0; m < 4; ++m)
                ldsm_x4(a[m], aA + (unsigned)(m * 16 * 72 * 2) + kk * 32);
            #pragma unroll
            for (int n = 0; n < 4; ++n)
                ldsm_x4(bb[n], aB + (unsigned)(n * 16 * 72 * 2) + kk * 32);
            #pragma unroll
            for (int m = 0; m < 4; ++m)
                #pragma unroll
                for (int n = 0; n < 4; ++n) {
                    mma_f16(acc[m][n * 2 + 0], a[m], bb[n][0], bb[n][2]);
                    mma_f16(acc[m][n * 2 + 1], a[m], bb[n][1], bb[n][3]);
                }
        }
        __syncthreads();
    }

    __half* tb = g_t_h + (size_t)b * C * HW;
    const float* nb = g_norm + (size_t)b * HW;
    #pragma unroll
    for (int m = 0; m < 4; ++m) {
        const int c0 = wm * 64 + m * 16 + (lane >> 2);
        const float bo0 = __ldg(bias + c0);
        const float bo1 = __ldg(bias + c0 + 8);
        #pragma unroll
        for (int t = 0; t < 8; ++t) {
            const int p = p0 + wn * 64 + t * 8 + (lane & 3) * 2;
            float2 n2 = *reinterpret_cast<const float2*>(nb + p);
            *reinterpret_cast<unsigned*>(tb + (size_t)c0 * HW + p) =
                pack_h2(acc[m][t][0] * n2.x + bo0, acc[m][t][1] * n2.y + bo0);
            *reinterpret_cast<unsigned*>(tb + (size_t)(c0 + 8) * HW + p) =
                pack_h2(acc[m][t][2] * n2.x + bo1, acc[m][t][3] * n2.y + bo1);
        }
    }
}

// ---------------------------------------------------------------------------
// qbuild: per (pair, b): S = Xn_i Xn_j^T (128x128, K=256 in four 64-chunks,
//         double-buffered), Q = S^2 -> g_Q[i][j].  Pairs with ti >= tj.
// smem halves: xi 2x(128x72), xj 2x(128x72), qs 128x136 = 108,544 B -> 2 CTAs
// ---------------------------------------------------------------------------
#define QB_XI0 0
#define QB_XI1 9216
#define QB_XJ0 18432
#define QB_XJ1 27648
#define QB_QS  36864
#define Q_SMEM_H 54272

__global__ void __launch_bounds__(256, 2)
qbuild_kernel()
{
    extern __shared__ __half smh[];
    const unsigned sbase = smem_u32(smh);

    const int p   = blockIdx.x;
    const int b   = blockIdx.y;
    const int tid = threadIdx.x;
    const int wid = tid >> 5;
    const int lane = tid & 31;

    // closed-form triangular index (with safety correction)
    int ti = (int)((sqrtf(8.f * (float)p + 1.f) - 1.f) * 0.5f);
    while ((ti + 1) * (ti + 2) / 2 <= p) ++ti;
    while (ti * (ti + 1) / 2 > p) --ti;
    const int tj = p - ti * (ti + 1) / 2;
    const int i0 = ti * TI;
    const int j0 = tj * TI;

    const __half* xnT_b = g_xnT_h + (size_t)b * HW * C;

    const int wm = wid & 3;    // i-strip (32 rows)
    const int wn = wid >> 2;   // j-half (64 cols)
    const unsigned lrow = (unsigned)(lane & 15);
    const unsigned lk8  = (unsigned)((lane >> 4) * 8);

    auto issue = [&](int kc) {
        const int kb = kc * 64;
        const unsigned xi_o = (unsigned)((kc & 1) ? QB_XI1 : QB_XI0);
        const unsigned xj_o = (unsigned)((kc & 1) ? QB_XJ1 : QB_XJ0);
        #pragma unroll
        for (int r = 0; r < 4; ++r) {
            int f = r * 256 + tid;
            int row = f >> 3, ch = f & 7;
            cpa16(sbase + (xi_o + (unsigned)(row * 72 + ch * 8)) * 2,
                  xnT_b + (size_t)(i0 + row) * C + kb + ch * 8);
            cpa16(sbase + (xj_o + (unsigned)(row * 72 + ch * 8)) * 2,
                  xnT_b + (size_t)(j0 + row) * C + kb + ch * 8);
        }
        cpa_commit();
    };

    issue(0);

    float d[2][8][4];
    #pragma unroll
    for (int m = 0; m < 2; ++m)
        #pragma unroll
        for (int t = 0; t < 8; ++t)
            #pragma unroll
            for (int r = 0; r < 4; ++r) d[m][t][r] = 0.f;

    for (int kc = 0; kc < 4; ++kc) {
        if (kc + 1 < 4) {
            issue(kc + 1);
            asm volatile("cp.async.wait_group 1;" ::: "memory");
        } else {
            asm volatile("cp.async.wait_group 0;" ::: "memory");
        }
        __syncthreads();

        const unsigned xi_o = (unsigned)((kc & 1) ? QB_XI1 : QB_XI0);
        const unsigned xj_o = (unsigned)((kc & 1) ? QB_XJ1 : QB_XJ0);
        const unsigned aA = sbase + (xi_o + (unsigned)((wm * 32 + lrow) * 72) + lk8) * 2;

        #pragma unroll
        for (int kk = 0; kk < 4; ++kk) {
            unsigned a[2][4];
            ldsm_x4(a[0], aA + kk * 32);
            ldsm_x4(a[1], aA + 16 * 72 * 2 + kk * 32);
            #pragma unroll
            for (int tt = 0; tt < 4; ++tt) {
                unsigned bb[4];
                ldsm_x4(bb, sbase + (xj_o + (unsigned)((wn * 64 + tt * 16 + lrow) * 72) + lk8) * 2
                             + kk * 32);
                #pragma unroll
                for (int m = 0; m < 2; ++m) {
                    mma_f16(d[m][tt * 2 + 0], a[m], bb[0], bb[2]);
                    mma_f16(d[m][tt * 2 + 1], a[m], bb[1], bb[3]);
                }
            }
        }
        __syncthreads();   // all warps done with this buffer before next overwrite
    }

    // square -> qs (stride 136)
    {
        __half* qsm = smh + QB_QS;
        #pragma unroll
        for (int m = 0; m < 2; ++m) {
            const int r0 = wm * 32 + m * 16 + (lane >> 2);
            #pragma unroll
            for (int t = 0; t < 8; ++t) {
                const int col = wn * 64 + t * 8 + (lane & 3) * 2;
                *reinterpret_cast<unsigned*>(qsm + r0 * 136 + col) =
                    pack_h2(d[m][t][0] * d[m][t][0], d[m][t][1] * d[m][t][1]);
                *reinterpret_cast<unsigned*>(qsm + (r0 + 8) * 136 + col) =
                    pack_h2(d[m][t][2] * d[m][t][2], d[m][t][3] * d[m][t][3]);
            }
        }
    }
    __syncthreads();

    __half* Qb = g_Q + ((size_t)b * HW * HW);
    #pragma unroll
    for (int rr = 0; rr < 16; ++rr) {
        const int r = wid * 16 + rr;
        uint2 v = *reinterpret_cast<const uint2*>(smh + QB_QS + r * 136 + lane * 4);
        *reinterpret_cast<uint2*>(Qb + (size_t)(i0 + r) * HW + j0 + lane * 4) = v;
    }
}

// ---------------------------------------------------------------------------
// propagate: out[b][c][j] = sum_k t[c][k] * Q_sym[k][j]
// CTA: 256 c x 128 j, 512 threads (4x4 warp grid), K=4096 in 64-chunks, db.
// smem halves: A 2x(256x72)=36864, B 2x9216=18432 -> 110,592 B, 1 CTA/SM.
// ---------------------------------------------------------------------------
#define P_A0 0
#define P_AB 18432
#define P_B0 36864
#define P_BB 9216
#define P_SMEM_H 55296

__global__ void __launch_bounds__(512, 1)
prop_kernel(float* __restrict__ out)
{
    extern __shared__ __half smh[];
    const unsigned sbase = smem_u32(smh);

    const int jt  = blockIdx.x;              // j-tile (128)
    const int b   = blockIdx.y;
    const int j0  = jt * TI;
    const int tid = threadIdx.x;
    const int wid = tid >> 5;
    const int lane = tid & 31;

    const int wc = wid & 3;    // c-group (64)
    const int wj = wid >> 2;   // j-group (32)
    const unsigned lrow = (unsigned)(lane & 15);
    const unsigned lk8  = (unsigned)((lane >> 4) * 8);
    const unsigned qrow = (unsigned)((((lane >> 3) & 1) * 8) + (lane & 7));

    const __half* t_b = g_t_h + (size_t)b * C * HW;
    const __half* Qb  = g_Q + ((size_t)b * HW * HW);

    auto issue = [&](int ck) {
        const int k0 = ck * 64;
        const int kb = k0 >> 7;
        const unsigned a_o = (unsigned)(P_A0 + (ck & 1) * P_AB);
        const unsigned b_o = (unsigned)(P_B0 + (ck & 1) * P_BB);
        // A: t rows c (256) x 64 k
        #pragma unroll
        for (int r = 0; r < 4; ++r) {
            int f = r * 512 + tid;
            int row = f >> 3, ch = f & 7;
            cpa16(sbase + (a_o + (unsigned)(row * 72 + ch * 8)) * 2,
                  t_b + (size_t)row * HW + k0 + ch * 8);
        }
        if (kb >= jt) {
            // k-major tile: 64 rows(k) x 128 cols(j), stride 136
            #pragma unroll
            for (int r = 0; r < 2; ++r) {
                int f = r * 512 + tid;
                int row = f >> 4, ch = f & 15;
                cpa16(sbase + (b_o + (unsigned)(row * 136 + ch * 8)) * 2,
                      Qb + (size_t)(k0 + row) * HW + j0 + ch * 8);
            }
        } else {
            // j-major tile: 128 rows(j) x 64 cols(k), stride 72
            #pragma unroll
            for (int r = 0; r < 2; ++r) {
                int f = r * 512 + tid;
                int row = f >> 3, ch = f & 7;
                cpa16(sbase + (b_o + (unsigned)(row * 72 + ch * 8)) * 2,
                      Qb + (size_t)(j0 + row) * HW + k0 + ch * 8);
            }
        }
        cpa_commit();
    };

    issue(0);

    float acc[4][4][4];
    #pragma unroll
    for (int s = 0; s < 4; ++s)
        #pragma unroll
        for (int t = 0; t < 4; ++t)
            #pragma unroll
            for (int r = 0; r < 4; ++r) acc[s][t][r] = 0.f;

    for (int ck = 0; ck < HW / 64; ++ck) {
        if (ck + 1 < HW / 64) {
            issue(ck + 1);
            asm volatile("cp.async.wait_group 1;" ::: "memory");
        } else {
            asm volatile("cp.async.wait_group 0;" ::: "memory");
        }
        __syncthreads();

        const int k0 = ck * 64;
        const int kb = k0 >> 7;
        const unsigned a_o = (unsigned)(P_A0 + (ck & 1) * P_AB);
        const unsigned b_o = (unsigned)(P_B0 + (ck & 1) * P_BB);
        const unsigned aA = sbase + (a_o + (unsigned)((wc * 64 + lrow) * 72) + lk8) * 2;

        if (kb >= jt) {
            #pragma unroll
            for (int kk = 0; kk < 4; ++kk) {
                unsigned aa[4][4];
                #pragma unroll
                for (int s = 0; s < 4; ++s)
                    ldsm_x4(aa[s], aA + (unsigned)(s * 16 * 72 * 2) + kk * 32);
                #pragma unroll
                for (int tp = 0; tp < 2; ++tp) {
                    unsigned bq[4];
                    ldsm_x4t(bq, sbase + (b_o + (unsigned)((kk * 16 + qrow) * 136 +
                                                           wj * 32 + tp * 16) + lk8) * 2);
                    #pragma unroll
                    for (int s = 0; s < 4; ++s) {
                        mma_f16(acc[s][tp * 2 + 0], aa[s], bq[0], bq[1]);
                        mma_f16(acc[s][tp * 2 + 1], aa[s], bq[2], bq[3]);
                    }
                }
            }
        } else {
            #pragma unroll
            for (int kk = 0; kk < 4; ++kk) {
                unsigned aa[4][4];
                #pragma unroll
                for (int s = 0; s < 4; ++s)
                    ldsm_x4(aa[s], aA + (unsigned)(s * 16 * 72 * 2) + kk * 32);
                #pragma unroll
                for (int tt = 0; tt < 2; ++tt) {
                    unsigned bb[4];
                    ldsm_x4(bb, sbase + (b_o + (unsigned)((wj * 32 + tt * 16 + lrow) * 72) +
                                         (unsigned)(kk * 16) + lk8) * 2);
                    #pragma unroll
                    for (int s = 0; s < 4; ++s) {
                        mma_f16(acc[s][tt * 2 + 0], aa[s], bb[0], bb[2]);
                        mma_f16(acc[s][tt * 2 + 1], aa[s], bb[1], bb[3]);
                    }
                }
            }
        }
        __syncthreads();
    }

    float* ob = out + (size_t)b * C * HW;
    #pragma unroll
    for (int s = 0; s < 4; ++s) {
        const int c0 = wc * 64 + s * 16 + (lane >> 2);
        #pragma unroll
        for (int t = 0; t < 4; ++t) {
            const int col = j0 + wj * 32 + t * 8 + (lane & 3) * 2;
            *reinterpret_cast<float2*>(ob + (size_t)c0 * HW + col) =
                make_float2(acc[s][t][0], acc[s][t][1]);
            *reinterpret_cast<float2*>(ob + (size_t)(c0 + 8) * HW + col) =
                make_float2(acc[s][t][2], acc[s][t][3]);
        }
    }
}

// ---------------------------------------------------------------------------
extern "C" void kernel_launch(void* const* d_in, const int* in_sizes, int n_in,
                              void* d_out, int out_size)
{
    const float* x    = (const float*)d_in[0];
    const float* W    = (const float*)d_in[1];
    const float* bias = (const float*)d_in[2];
    float* out        = (float*)d_out;

    const int PREP_SMEM = (C * 68 + 64) * 4;
    const int TG_SMEM   = TG_SMEM_H * 2;
    const int Q_SMEM    = Q_SMEM_H * 2;      // 108,544 B -> 2 CTAs/SM
    const int P_SMEM    = P_SMEM_H * 2;      // 110,592 B -> 1 CTA/SM (512 thr)

    cudaFuncSetAttribute(prep_kernel,   cudaFuncAttributeMaxDynamicSharedMemorySize, PREP_SMEM);
    cudaFuncSetAttribute(tgemm_kernel,  cudaFuncAttributeMaxDynamicSharedMemorySize, TG_SMEM);
    cudaFuncSetAttribute(qbuild_kernel, cudaFuncAttributeMaxDynamicSharedMemorySize, Q_SMEM);
    cudaFuncSetAttribute(prop_kernel,   cudaFuncAttributeMaxDynamicSharedMemorySize, P_SMEM);

    conv_w_kernel<<<64, 256>>>(W);

    dim3 g1(HW / PT, BATCH);
    prep_kernel<<<g1, 256, PREP_SMEM>>>(x);

    dim3 gt(HW / 128, BATCH);
    tgemm_kernel<<<gt, 256, TG_SMEM>>>(bias);

    dim3 gq(NPAIR, BATCH);
    qbuild_kernel<<<gq, 256, Q_SMEM>>>();

    dim3 gp(NTI, BATCH);
    prop_kernel<<<gp, 512, P_SMEM>>>(out);
}

// round 11
// speedup vs baseline: 10.9493x; 1.0352x over previous
#include <cuda_runtime.h>
#include <cuda_fp16.h>

#define BATCH 8
#define C 256
#define HW 4096
#define PT 64
#define TI 128
#define NTI (HW / TI)                // 32
#define NPAIR (NTI * (NTI + 1) / 2)  // 528

// Global scratch
__device__ __half g_xnT_h[(size_t)BATCH * HW * C];  // normalized, pixel-major (p, c)
__device__ float  g_norm [(size_t)BATCH * HW];      // channel L2 norm per pixel
__device__ __half g_t_h  [(size_t)BATCH * C * HW];  // t = Wx+b, c-major (c, p)
__device__ __half g_W_h  [C * C];                   // W fp16
__device__ __half g_Q    [(size_t)BATCH * HW * HW]; // Q = S^2, lower-block-triangle only

__device__ __forceinline__ unsigned smem_u32(const void* p) {
    unsigned a;
    asm("{ .reg .u64 t; cvta.to.shared.u64 t, %1; cvt.u32.u64 %0, t; }" : "=r"(a) : "l"(p));
    return a;
}
__device__ __forceinline__ void cpa16(unsigned dst, const void* src) {
    asm volatile("cp.async.cg.shared.global [%0], [%1], 16;" :: "r"(dst), "l"(src) : "memory");
}
__device__ __forceinline__ void cpa_commit() {
    asm volatile("cp.async.commit_group;" ::: "memory");
}
__device__ __forceinline__ void ldsm_x4(unsigned* r, unsigned addr) {
    asm volatile("ldmatrix.sync.aligned.m8n8.x4.shared.b16 {%0,%1,%2,%3}, [%4];"
                 : "=r"(r[0]), "=r"(r[1]), "=r"(r[2]), "=r"(r[3]) : "r"(addr));
}
__device__ __forceinline__ void ldsm_x4t(unsigned* r, unsigned addr) {
    asm volatile("ldmatrix.sync.aligned.m8n8.x4.trans.shared.b16 {%0,%1,%2,%3}, [%4];"
                 : "=r"(r[0]), "=r"(r[1]), "=r"(r[2]), "=r"(r[3]) : "r"(addr));
}
__device__ __forceinline__ void mma_f16(float d[4], const unsigned a[4], unsigned b0, unsigned b1) {
    asm volatile(
        "mma.sync.aligned.m16n8k16.row.col.f32.f16.f16.f32 "
        "{%0,%1,%2,%3}, {%4,%5,%6,%7}, {%8,%9}, {%0,%1,%2,%3};"
        : "+f"(d[0]), "+f"(d[1]), "+f"(d[2]), "+f"(d[3])
        : "r"(a[0]), "r"(a[1]), "r"(a[2]), "r"(a[3]), "r"(b0), "r"(b1));
}
__device__ __forceinline__ unsigned pack_h2(float a, float b) {
    __half2 h = __floats2half2_rn(a, b);
    return *reinterpret_cast<unsigned*>(&h);
}

// ---------------------------------------------------------------------------
__global__ void conv_w_kernel(const float* __restrict__ W) {
    int i = (blockIdx.x * 256 + threadIdx.x) * 4;
    float4 v = *reinterpret_cast<const float4*>(W + i);
    uint2 u;
    u.x = pack_h2(v.x, v.y);
    u.y = pack_h2(v.z, v.w);
    *reinterpret_cast<uint2*>(g_W_h + i) = u;
}

// ---------------------------------------------------------------------------
// Prep: invn + write xnT_h (normalized, fp16) + g_norm (fp32)
// ---------------------------------------------------------------------------
__global__ void __launch_bounds__(256, 1)
prep_kernel(const float* __restrict__ x)
{
    extern __shared__ float sm[];
    float* xs   = sm;                  // C * 68
    float* invn = xs + C * 68;         // 64

    const int p0  = blockIdx.x * PT;
    const int b   = blockIdx.y;
    const int tid = threadIdx.x;
    const float* xb = x + (size_t)b * C * HW;

    #pragma unroll
    for (int r = 0; r < 16; ++r) {
        int f4 = r * 256 + tid;
        int c  = f4 >> 4;
        int kq = f4 & 15;
        float4 v = *reinterpret_cast<const float4*>(xb + (size_t)c * HW + p0 + kq * 4);
        *reinterpret_cast<float4*>(xs + c * 68 + kq * 4) = v;
    }
    __syncthreads();

    if (tid < 64) {
        float s = 0.f;
        #pragma unroll 8
        for (int c = 0; c < C; ++c) { float v = xs[c * 68 + tid]; s += v * v; }
        float nrm = fmaxf(sqrtf(s), 1e-12f);
        g_norm[(size_t)b * HW + p0 + tid] = nrm;
        invn[tid] = 1.0f / nrm;
    }
    __syncthreads();

    {
        int p   = tid & 63;
        int grp = tid >> 6;
        float inv = invn[p];
        __half* dn = g_xnT_h + ((size_t)b * HW + p0 + p) * C;
        #pragma unroll
        for (int cc = 0; cc < 16; ++cc) {
            int c = grp * 64 + cc * 4;
            uint2 un;
            un.x = pack_h2(xs[(c + 0) * 68 + p] * inv, xs[(c + 1) * 68 + p] * inv);
            un.y = pack_h2(xs[(c + 2) * 68 + p] * inv, xs[(c + 3) * 68 + p] * inv);
            *reinterpret_cast<uint2*>(dn + c) = un;
        }
    }
}

// ---------------------------------------------------------------------------
// tgemm: t[c][p] = norm[p] * (W @ xn)[c][p] + bias[c]
// ---------------------------------------------------------------------------
#define TG_WS 18432
#define TG_XS 9216
#define TG_SMEM_H (2 * TG_WS + 2 * TG_XS)

__global__ void __launch_bounds__(256, 1)
tgemm_kernel(const float* __restrict__ bias)
{
    extern __shared__ __half smh[];
    const unsigned sbase = smem_u32(smh);

    const int p0  = blockIdx.x * 128;
    const int b   = blockIdx.y;
    const int tid = threadIdx.x;
    const int wid = tid >> 5;
    const int lane = tid & 31;
    const int wm = wid & 3;
    const int wn = wid >> 2;
    const unsigned lrow = (unsigned)(lane & 15);
    const unsigned lk8  = (unsigned)((lane >> 4) * 8);

    const __half* xn_b = g_xnT_h + (size_t)b * HW * C;

    auto issue = [&](int ck) {
        const int k0 = ck * 64;
        const unsigned ws_o = (unsigned)((ck & 1) * TG_WS);
        const unsigned xs_o = (unsigned)(2 * TG_WS + (ck & 1) * TG_XS);
        #pragma unroll
        for (int r = 0; r < 8; ++r) {
            int f = r * 256 + tid;
            int c = f >> 3, ch = f & 7;
            cpa16(sbase + (ws_o + (unsigned)(c * 72 + ch * 8)) * 2,
                  g_W_h + (size_t)c * C + k0 + ch * 8);
        }
        #pragma unroll
        for (int r = 0; r < 4; ++r) {
            int f = r * 256 + tid;
            int p = f >> 3, ch = f & 7;
            cpa16(sbase + (xs_o + (unsigned)(p * 72 + ch * 8)) * 2,
                  xn_b + (size_t)(p0 + p) * C + k0 + ch * 8);
        }
        cpa_commit();
    };

    issue(0);

    float acc[4][8][4];
    #pragma unroll
    for (int m = 0; m < 4; ++m)
        #pragma unroll
        for (int t = 0; t < 8; ++t)
            #pragma unroll
            for (int r = 0; r < 4; ++r) acc[m][t][r] = 0.f;

    for (int ck = 0; ck < 4; ++ck) {
        if (ck + 1 < 4) {
            issue(ck + 1);
            asm volatile("cp.async.wait_group 1;" ::: "memory");
        } else {
            asm volatile("cp.async.wait_group 0;" ::: "memory");
        }
        __syncthreads();
        const unsigned ws_o = (unsigned)((ck & 1) * TG_WS);
        const unsigned xs_o = (unsigned)(2 * TG_WS + (ck & 1) * TG_XS);

        const unsigned aA = sbase + (ws_o + (unsigned)((wm * 64 + lrow) * 72) + lk8) * 2;
        const unsigned aB = sbase + (xs_o + (unsigned)((wn * 64 + lrow) * 72) + lk8) * 2;
        #pragma unroll
        for (int kk = 0; kk < 4; ++kk) {
            unsigned a[4][4], bb[4][4];
            #pragma unroll
            for (int m = 0; m < 4; ++m)
                ldsm_x4(a[m], aA + (unsigned)(m * 16 * 72 * 2) + kk * 32);
            #pragma unroll
            for (int n = 0; n < 4; ++n)
                ldsm_x4(bb[n], aB + (unsigned)(n * 16 * 72 * 2) + kk * 32);
            #pragma unroll
            for (int m = 0; m < 4; ++m)
                #pragma unroll
                for (int n = 0; n < 4; ++n) {
                    mma_f16(acc[m][n * 2 + 0], a[m], bb[n][0], bb[n][2]);
                    mma_f16(acc[m][n * 2 + 1], a[m], bb[n][1], bb[n][3]);
                }
        }
        __syncthreads();
    }

    __half* tb = g_t_h + (size_t)b * C * HW;
    const float* nb = g_norm + (size_t)b * HW;
    #pragma unroll
    for (int m = 0; m < 4; ++m) {
        const int c0 = wm * 64 + m * 16 + (lane >> 2);
        const float bo0 = __ldg(bias + c0);
        const float bo1 = __ldg(bias + c0 + 8);
        #pragma unroll
        for (int t = 0; t < 8; ++t) {
            const int p = p0 + wn * 64 + t * 8 + (lane & 3) * 2;
            float2 n2 = *reinterpret_cast<const float2*>(nb + p);
            *reinterpret_cast<unsigned*>(tb + (size_t)c0 * HW + p) =
                pack_h2(acc[m][t][0] * n2.x + bo0, acc[m][t][1] * n2.y + bo0);
            *reinterpret_cast<unsigned*>(tb + (size_t)(c0 + 8) * HW + p) =
                pack_h2(acc[m][t][2] * n2.x + bo1, acc[m][t][3] * n2.y + bo1);
        }
    }
}

// ---------------------------------------------------------------------------
// qbuild: per (pair, b): S = Xn_i Xn_j^T (128x128, K=256 in four 64-chunks,
//         double-buffered), Q = S^2 -> g_Q[i][j].  Pairs with ti >= tj.
// smem halves: xi 2x(128x72), xj 2x(128x72), qs 128x136 = 108,544 B -> 2 CTAs
// ---------------------------------------------------------------------------
#define QB_XI0 0
#define QB_XI1 9216
#define QB_XJ0 18432
#define QB_XJ1 27648
#define QB_QS  36864
#define Q_SMEM_H 54272

__global__ void __launch_bounds__(256, 2)
qbuild_kernel()
{
    extern __shared__ __half smh[];
    const unsigned sbase = smem_u32(smh);

    const int p   = blockIdx.x;
    const int b   = blockIdx.y;
    const int tid = threadIdx.x;
    const int wid = tid >> 5;
    const int lane = tid & 31;

    int ti = (int)((sqrtf(8.f * (float)p + 1.f) - 1.f) * 0.5f);
    while ((ti + 1) * (ti + 2) / 2 <= p) ++ti;
    while (ti * (ti + 1) / 2 > p) --ti;
    const int tj = p - ti * (ti + 1) / 2;
    const int i0 = ti * TI;
    const int j0 = tj * TI;

    const __half* xnT_b = g_xnT_h + (size_t)b * HW * C;

    const int wm = wid & 3;    // i-strip (32 rows)
    const int wn = wid >> 2;   // j-half (64 cols)
    const unsigned lrow = (unsigned)(lane & 15);
    const unsigned lk8  = (unsigned)((lane >> 4) * 8);

    auto issue = [&](int kc) {
        const int kb = kc * 64;
        const unsigned xi_o = (unsigned)((kc & 1) ? QB_XI1 : QB_XI0);
        const unsigned xj_o = (unsigned)((kc & 1) ? QB_XJ1 : QB_XJ0);
        #pragma unroll
        for (int r = 0; r < 4; ++r) {
            int f = r * 256 + tid;
            int row = f >> 3, ch = f & 7;
            cpa16(sbase + (xi_o + (unsigned)(row * 72 + ch * 8)) * 2,
                  xnT_b + (size_t)(i0 + row) * C + kb + ch * 8);
            cpa16(sbase + (xj_o + (unsigned)(row * 72 + ch * 8)) * 2,
                  xnT_b + (size_t)(j0 + row) * C + kb + ch * 8);
        }
        cpa_commit();
    };

    issue(0);

    float d[2][8][4];
    #pragma unroll
    for (int m = 0; m < 2; ++m)
        #pragma unroll
        for (int t = 0; t < 8; ++t)
            #pragma unroll
            for (int r = 0; r < 4; ++r) d[m][t][r] = 0.f;

    for (int kc = 0; kc < 4; ++kc) {
        if (kc + 1 < 4) {
            issue(kc + 1);
            asm volatile("cp.async.wait_group 1;" ::: "memory");
        } else {
            asm volatile("cp.async.wait_group 0;" ::: "memory");
        }
        __syncthreads();

        const unsigned xi_o = (unsigned)((kc & 1) ? QB_XI1 : QB_XI0);
        const unsigned xj_o = (unsigned)((kc & 1) ? QB_XJ1 : QB_XJ0);
        const unsigned aA = sbase + (xi_o + (unsigned)((wm * 32 + lrow) * 72) + lk8) * 2;
        const unsigned aB = sbase + (xj_o + (unsigned)((wn * 64 + lrow) * 72) + lk8) * 2;

        #pragma unroll
        for (int kk = 0; kk < 4; ++kk) {
            unsigned a[2][4];
            ldsm_x4(a[0], aA + kk * 32);
            ldsm_x4(a[1], aA + 16 * 72 * 2 + kk * 32);
            #pragma unroll
            for (int tt = 0; tt < 4; ++tt) {
                unsigned bb[4];
                ldsm_x4(bb, aB + (unsigned)(tt * 16 * 72 * 2) + kk * 32);
                #pragma unroll
                for (int m = 0; m < 2; ++m) {
                    mma_f16(d[m][tt * 2 + 0], a[m], bb[0], bb[2]);
                    mma_f16(d[m][tt * 2 + 1], a[m], bb[1], bb[3]);
                }
            }
        }
        __syncthreads();
    }

    {
        __half* qsm = smh + QB_QS;
        #pragma unroll
        for (int m = 0; m < 2; ++m) {
            const int r0 = wm * 32 + m * 16 + (lane >> 2);
            #pragma unroll
            for (int t = 0; t < 8; ++t) {
                const int col = wn * 64 + t * 8 + (lane & 3) * 2;
                *reinterpret_cast<unsigned*>(qsm + r0 * 136 + col) =
                    pack_h2(d[m][t][0] * d[m][t][0], d[m][t][1] * d[m][t][1]);
                *reinterpret_cast<unsigned*>(qsm + (r0 + 8) * 136 + col) =
                    pack_h2(d[m][t][2] * d[m][t][2], d[m][t][3] * d[m][t][3]);
            }
        }
    }
    __syncthreads();

    __half* Qb = g_Q + ((size_t)b * HW * HW);
    #pragma unroll
    for (int rr = 0; rr < 16; ++rr) {
        const int r = wid * 16 + rr;
        uint2 v = *reinterpret_cast<const uint2*>(smh + QB_QS + r * 136 + lane * 4);
        *reinterpret_cast<uint2*>(Qb + (size_t)(i0 + r) * HW + j0 + lane * 4) = v;
    }
}

// ---------------------------------------------------------------------------
// propagate: out[b][c][j] = sum_k t[c][k] * Q_sym[k][j]
// CTA: 128 c x 128 j, 256 threads, 2 CTAs/SM, K=4096 in 64-chunks,
// THREE-stage cp.async pipeline (prefetch 2 chunks ahead; Q misses L2).
// smem halves: A 3x9216 + B 3x9216 = 55296 -> 110,592 B per CTA.
// ---------------------------------------------------------------------------
#define P_AS 9216
#define P_BS 9216
#define P_SMEM_H (6 * 9216)

__global__ void __launch_bounds__(256, 2)
prop_kernel(float* __restrict__ out)
{
    extern __shared__ __half smh[];
    const unsigned sbase = smem_u32(smh);

    const int cs  = blockIdx.x & 1;          // c-strip (128)
    const int jt  = blockIdx.x >> 1;         // j-tile (128)
    const int b   = blockIdx.y;
    const int j0  = jt * TI;
    const int tid = threadIdx.x;
    const int wid = tid >> 5;
    const int lane = tid & 31;

    const int wc = wid & 1;    // c-half (64)
    const int wj = wid >> 1;   // j-quarter (32)
    const unsigned lrow = (unsigned)(lane & 15);
    const unsigned lk8  = (unsigned)((lane >> 4) * 8);
    const unsigned qrow = (unsigned)((((lane >> 3) & 1) * 8) + (lane & 7));

    const __half* t_b = g_t_h + (size_t)b * C * HW;
    const __half* Qb  = g_Q + ((size_t)b * HW * HW);

    auto issue = [&](int ck) {
        const int k0 = ck * 64;
        const int kb = k0 >> 7;
        const int s  = ck % 3;
        const unsigned a_o = (unsigned)(s * P_AS);
        const unsigned b_o = (unsigned)(3 * P_AS + s * P_BS);
        #pragma unroll
        for (int r = 0; r < 4; ++r) {
            int f = r * 256 + tid;
            int row = f >> 3, ch = f & 7;
            cpa16(sbase + (a_o + (unsigned)(row * 72 + ch * 8)) * 2,
                  t_b + (size_t)(cs * 128 + row) * HW + k0 + ch * 8);
        }
        if (kb >= jt) {
            // k-major tile: 64 rows(k) x 128 cols(j), stride 136
            #pragma unroll
            for (int r = 0; r < 4; ++r) {
                int f = r * 256 + tid;
                int row = f >> 4, ch = f & 15;
                cpa16(sbase + (b_o + (unsigned)(row * 136 + ch * 8)) * 2,
                      Qb + (size_t)(k0 + row) * HW + j0 + ch * 8);
            }
        } else {
            // j-major tile: 128 rows(j) x 64 cols(k), stride 72
            #pragma unroll
            for (int r = 0; r < 4; ++r) {
                int f = r * 256 + tid;
                int row = f >> 3, ch = f & 7;
                cpa16(sbase + (b_o + (unsigned)(row * 72 + ch * 8)) * 2,
                      Qb + (size_t)(j0 + row) * HW + k0 + ch * 8);
            }
        }
        cpa_commit();
    };

    issue(0);
    issue(1);

    float acc[4][4][4];
    #pragma unroll
    for (int s = 0; s < 4; ++s)
        #pragma unroll
        for (int t = 0; t < 4; ++t)
            #pragma unroll
            for (int r = 0; r < 4; ++r) acc[s][t][r] = 0.f;

    const unsigned aAinv = sbase + ((unsigned)((wc * 64 + lrow) * 72) + lk8) * 2;

    for (int ck = 0; ck < HW / 64; ++ck) {
        if (ck == HW / 64 - 1) {
            asm volatile("cp.async.wait_group 0;" ::: "memory");
        } else {
            asm volatile("cp.async.wait_group 1;" ::: "memory");
        }
        __syncthreads();   // chunk ck ready; all warps done with buf((ck+2)%3)

        if (ck + 2 < HW / 64) issue(ck + 2);

        const int k0 = ck * 64;
        const int kb = k0 >> 7;
        const int sb = ck % 3;
        const unsigned a_o = (unsigned)(sb * P_AS);
        const unsigned b_o = (unsigned)(3 * P_AS + sb * P_BS);
        const unsigned aA = aAinv + a_o * 2;

        if (kb >= jt) {
            #pragma unroll
            for (int kk = 0; kk < 4; ++kk) {
                unsigned aa[4][4];
                #pragma unroll
                for (int s = 0; s < 4; ++s)
                    ldsm_x4(aa[s], aA + (unsigned)(s * 16 * 72 * 2) + kk * 32);
                #pragma unroll
                for (int tp = 0; tp < 2; ++tp) {
                    unsigned bq[4];
                    ldsm_x4t(bq, sbase + (b_o + (unsigned)((kk * 16 + qrow) * 136 +
                                                           wj * 32 + tp * 16) + lk8) * 2);
                    #pragma unroll
                    for (int s = 0; s < 4; ++s) {
                        mma_f16(acc[s][tp * 2 + 0], aa[s], bq[0], bq[1]);
                        mma_f16(acc[s][tp * 2 + 1], aa[s], bq[2], bq[3]);
                    }
                }
            }
        } else {
            #pragma unroll
            for (int kk = 0; kk < 4; ++kk) {
                unsigned aa[4][4];
                #pragma unroll
                for (int s = 0; s < 4; ++s)
                    ldsm_x4(aa[s], aA + (unsigned)(s * 16 * 72 * 2) + kk * 32);
                #pragma unroll
                for (int tt = 0; tt < 2; ++tt) {
                    unsigned bb[4];
                    ldsm_x4(bb, sbase + (b_o + (unsigned)((wj * 32 + tt * 16 + lrow) * 72) +
                                         (unsigned)(kk * 16) + lk8) * 2);
                    #pragma unroll
                    for (int s = 0; s < 4; ++s) {
                        mma_f16(acc[s][tt * 2 + 0], aa[s], bb[0], bb[2]);
                        mma_f16(acc[s][tt * 2 + 1], aa[s], bb[1], bb[3]);
                    }
                }
            }
        }
    }

    float* ob = out + (size_t)b * C * HW;
    #pragma unroll
    for (int s = 0; s < 4; ++s) {
        const int c0 = cs * 128 + wc * 64 + s * 16 + (lane >> 2);
        #pragma unroll
        for (int t = 0; t < 4; ++t) {
            const int col = j0 + wj * 32 + t * 8 + (lane & 3) * 2;
            *reinterpret_cast<float2*>(ob + (size_t)c0 * HW + col) =
                make_float2(acc[s][t][0], acc[s][t][1]);
            *reinterpret_cast<float2*>(ob + (size_t)(c0 + 8) * HW + col) =
                make_float2(acc[s][t][2], acc[s][t][3]);
        }
    }
}

// ---------------------------------------------------------------------------
extern "C" void kernel_launch(void* const* d_in, const int* in_sizes, int n_in,
                              void* d_out, int out_size)
{
    const float* x    = (const float*)d_in[0];
    const float* W    = (const float*)d_in[1];
    const float* bias = (const float*)d_in[2];
    float* out        = (float*)d_out;

    const int PREP_SMEM = (C * 68 + 64) * 4;
    const int TG_SMEM   = TG_SMEM_H * 2;
    const int Q_SMEM    = Q_SMEM_H * 2;      // 108,544 B -> 2 CTAs/SM
    const int P_SMEM    = P_SMEM_H * 2;      // 110,592 B -> 2 CTAs/SM

    cudaFuncSetAttribute(prep_kernel,   cudaFuncAttributeMaxDynamicSharedMemorySize, PREP_SMEM);
    cudaFuncSetAttribute(tgemm_kernel,  cudaFuncAttributeMaxDynamicSharedMemorySize, TG_SMEM);
    cudaFuncSetAttribute(qbuild_kernel, cudaFuncAttributeMaxDynamicSharedMemorySize, Q_SMEM);
    cudaFuncSetAttribute(prop_kernel,   cudaFuncAttributeMaxDynamicSharedMemorySize, P_SMEM);

    conv_w_kernel<<<64, 256>>>(W);

    dim3 g1(HW / PT, BATCH);
    prep_kernel<<<g1, 256, PREP_SMEM>>>(x);

    dim3 gt(HW / 128, BATCH);
    tgemm_kernel<<<gt, 256, TG_SMEM>>>(bias);

    dim3 gq(NPAIR, BATCH);
    qbuild_kernel<<<gq, 256, Q_SMEM>>>();

    dim3 gp(2 * NTI, BATCH);
    prop_kernel<<<gp, 256, P_SMEM>>>(out);
}